// round 2
// baseline (speedup 1.0000x reference)
#include <cuda_runtime.h>

// Problem constants
#define Bz    8
#define Nn    1024
#define DIMm  512
#define Hh    8
#define DHd   64
#define INNERi 512
#define NPp   1025     // 2*MAX_POS + 1
#define BHb   64       // Bz*Hh
#define MXm   8192     // Bz*Nn

// ---------------- device scratch (allocation-free rule: static globals) ----
__device__ float g_q  [(size_t)BHb * Nn * DHd];      // [b][h][n][d]   16.8 MB
__device__ float g_k  [(size_t)BHb * Nn * DHd];
__device__ float g_v  [(size_t)BHb * Nn * DHd];
__device__ float g_P  [(size_t)BHb * Nn * NPp];      // q . pos_table  268.7 MB
__device__ float g_S  [(size_t)BHb * Nn * Nn];       // scores/attn    268.4 MB
__device__ float g_ctx[(size_t)MXm * INNERi];        // [b][n][h][d]   16.8 MB

// ===========================================================================
// Kernel 1: fused QKV projection.
//   C[8192,1536] = x[8192,512] @ [Wq | Wkv]   then scatter into head layout.
// 64x64 tile, BK=16, 256 threads, 4x4 micro-tile.
// ===========================================================================
__global__ void qkv_kernel(const float* __restrict__ x,
                           const float* __restrict__ Wq,
                           const float* __restrict__ Wkv) {
    __shared__ __align__(16) float As[16][68];
    __shared__ __align__(16) float Bs[16][64];

    const int n0 = blockIdx.x * 64;   // 0..1535
    const int m0 = blockIdx.y * 64;   // 0..8191
    const int t  = threadIdx.x;
    const int tx = t & 15, ty = t >> 4;

    const float* Wsrc; int ldw, cbase;
    float* dst; int jbase;
    if (n0 < 512)       { Wsrc = Wq;  ldw = 512;  cbase = n0;       dst = g_q; jbase = 0;    }
    else if (n0 < 1024) { Wsrc = Wkv; ldw = 1024; cbase = n0 - 512; dst = g_k; jbase = 512;  }
    else                { Wsrc = Wkv; ldw = 1024; cbase = n0 - 512; dst = g_v; jbase = 1024; }

    float acc[4][4] = {};

    for (int k0 = 0; k0 < 512; k0 += 16) {
        #pragma unroll
        for (int i = 0; i < 4; i++) {
            int l = t + i * 256;
            int mm = l >> 4, kk = l & 15;
            As[kk][mm] = x[(m0 + mm) * 512 + k0 + kk];
        }
        #pragma unroll
        for (int i = 0; i < 4; i++) {
            int l = t + i * 256;
            int kk = l >> 6, nn = l & 63;
            Bs[kk][nn] = Wsrc[(k0 + kk) * ldw + cbase + nn];
        }
        __syncthreads();
        #pragma unroll
        for (int kk = 0; kk < 16; kk++) {
            float4 a4 = *(const float4*)&As[kk][ty * 4];
            float4 b4 = *(const float4*)&Bs[kk][tx * 4];
            float a[4] = {a4.x, a4.y, a4.z, a4.w};
            float b[4] = {b4.x, b4.y, b4.z, b4.w};
            #pragma unroll
            for (int ii = 0; ii < 4; ii++)
                #pragma unroll
                for (int jj = 0; jj < 4; jj++)
                    acc[ii][jj] += a[ii] * b[jj];
        }
        __syncthreads();
    }

    #pragma unroll
    for (int ii = 0; ii < 4; ii++) {
        int m  = m0 + ty * 4 + ii;
        int bb = m >> 10, nrow = m & 1023;
        #pragma unroll
        for (int jj = 0; jj < 4; jj++) {
            int j = n0 + tx * 4 + jj - jbase;    // 0..511 within region
            int h = j >> 6, d = j & 63;
            dst[(((size_t)(bb * 8 + h) * Nn + nrow) * DHd) + d] = acc[ii][jj];
        }
    }
}

// ===========================================================================
// Kernel 2: P[m,p] = q[m,:] . pos_table[p,:]   (m = bh*N + n, K = 64)
// ===========================================================================
__global__ void pos_gemm_kernel(const float* __restrict__ T) {
    __shared__ __align__(16) float Qs[64][68];
    __shared__ __align__(16) float Ts[64][68];

    const int p0 = blockIdx.x * 64;   // 0..1088 (17 tiles, last partial)
    const int m0 = blockIdx.y * 64;   // 0..65535
    const int t  = threadIdx.x;
    const int tx = t & 15, ty = t >> 4;

    #pragma unroll
    for (int i = 0; i < 16; i++) {
        int l = t + i * 256;
        int kk = l & 63, mm = l >> 6;
        Qs[kk][mm] = g_q[(size_t)(m0 + mm) * DHd + kk];
    }
    #pragma unroll
    for (int i = 0; i < 16; i++) {
        int l = t + i * 256;
        int kk = l & 63, nn = l >> 6;
        int p = p0 + nn;
        Ts[kk][nn] = (p < NPp) ? T[p * DHd + kk] : 0.0f;
    }
    __syncthreads();

    float acc[4][4] = {};
    #pragma unroll
    for (int kk = 0; kk < 64; kk++) {
        float4 a4 = *(const float4*)&Qs[kk][ty * 4];
        float4 b4 = *(const float4*)&Ts[kk][tx * 4];
        float a[4] = {a4.x, a4.y, a4.z, a4.w};
        float b[4] = {b4.x, b4.y, b4.z, b4.w};
        #pragma unroll
        for (int ii = 0; ii < 4; ii++)
            #pragma unroll
            for (int jj = 0; jj < 4; jj++)
                acc[ii][jj] += a[ii] * b[jj];
    }

    #pragma unroll
    for (int ii = 0; ii < 4; ii++) {
        int m = m0 + ty * 4 + ii;
        #pragma unroll
        for (int jj = 0; jj < 4; jj++) {
            int p = p0 + tx * 4 + jj;
            if (p < NPp) g_P[(size_t)m * NPp + p] = acc[ii][jj];
        }
    }
}

// ===========================================================================
// Kernel 3: S[bh,i,j] = scale * ( q_i . k_j  +  P[bh,i, clip(i-j)+512] )
// One 64x64 tile per block, K = 64 (single stage).
// ===========================================================================
__global__ void score_kernel(float scale) {
    __shared__ __align__(16) float Qs[64][68];
    __shared__ __align__(16) float Ks[64][68];

    const int j0 = blockIdx.x * 64;
    const int i0 = blockIdx.y * 64;
    const int bh = blockIdx.z;
    const int t  = threadIdx.x;
    const int tx = t & 15, ty = t >> 4;

    const float* qb = g_q + (size_t)bh * Nn * DHd;
    const float* kb = g_k + (size_t)bh * Nn * DHd;

    #pragma unroll
    for (int i = 0; i < 16; i++) {
        int l = t + i * 256;
        int kk = l & 63, mm = l >> 6;
        Qs[kk][mm] = qb[(i0 + mm) * DHd + kk];
    }
    #pragma unroll
    for (int i = 0; i < 16; i++) {
        int l = t + i * 256;
        int kk = l & 63, nn = l >> 6;
        Ks[kk][nn] = kb[(j0 + nn) * DHd + kk];
    }
    __syncthreads();

    float acc[4][4] = {};
    #pragma unroll
    for (int kk = 0; kk < 64; kk++) {
        float4 a4 = *(const float4*)&Qs[kk][ty * 4];
        float4 b4 = *(const float4*)&Ks[kk][tx * 4];
        float a[4] = {a4.x, a4.y, a4.z, a4.w};
        float b[4] = {b4.x, b4.y, b4.z, b4.w};
        #pragma unroll
        for (int ii = 0; ii < 4; ii++)
            #pragma unroll
            for (int jj = 0; jj < 4; jj++)
                acc[ii][jj] += a[ii] * b[jj];
    }

    const float* Pb = g_P + (size_t)bh * Nn * NPp;
    float* Sb = g_S + (size_t)bh * Nn * Nn;
    #pragma unroll
    for (int ii = 0; ii < 4; ii++) {
        int i = i0 + ty * 4 + ii;
        #pragma unroll
        for (int jj = 0; jj < 4; jj++) {
            int j = j0 + tx * 4 + jj;
            int delta = i - j;
            delta = max(-512, min(512, delta));
            float pv = Pb[(size_t)i * NPp + (delta + 512)];
            Sb[(size_t)i * Nn + j] = scale * (acc[ii][jj] + pv);
        }
    }
}

// ===========================================================================
// Kernel 4: row softmax over N=1024, in place on g_S. One block per row.
// ===========================================================================
__global__ void softmax_kernel() {
    __shared__ float redm[8];
    __shared__ float reds[8];
    const size_t row = blockIdx.x;
    float* S = g_S + row * (size_t)Nn;
    const int t = threadIdx.x;       // 256 threads * 4 floats
    const int lane = t & 31, warp = t >> 5;

    float4 v = *(float4*)(S + t * 4);
    float m = fmaxf(fmaxf(v.x, v.y), fmaxf(v.z, v.w));
    #pragma unroll
    for (int o = 16; o; o >>= 1) m = fmaxf(m, __shfl_xor_sync(0xffffffffu, m, o));
    if (lane == 0) redm[warp] = m;
    __syncthreads();
    float rowmax = redm[0];
    #pragma unroll
    for (int i = 1; i < 8; i++) rowmax = fmaxf(rowmax, redm[i]);

    float4 e;
    e.x = __expf(v.x - rowmax);
    e.y = __expf(v.y - rowmax);
    e.z = __expf(v.z - rowmax);
    e.w = __expf(v.w - rowmax);
    float s = e.x + e.y + e.z + e.w;
    #pragma unroll
    for (int o = 16; o; o >>= 1) s += __shfl_xor_sync(0xffffffffu, s, o);
    if (lane == 0) reds[warp] = s;
    __syncthreads();
    float tot = 0.0f;
    #pragma unroll
    for (int i = 0; i < 8; i++) tot += reds[i];
    float inv = 1.0f / tot;

    e.x *= inv; e.y *= inv; e.z *= inv; e.w *= inv;
    *(float4*)(S + t * 4) = e;
}

// ===========================================================================
// Kernel 5: ctx[b,n,h,d] = sum_j attn[bh,n,j] * v[bh,j,d]   (M=1024,N=64,K=1024)
// ===========================================================================
__global__ void av_kernel() {
    __shared__ __align__(16) float As[16][68];
    __shared__ __align__(16) float Vs[16][64];

    const int i0 = blockIdx.x * 64;
    const int bh = blockIdx.y;
    const int t  = threadIdx.x;
    const int tx = t & 15, ty = t >> 4;

    const float* Sb = g_S + (size_t)bh * Nn * Nn;
    const float* vb = g_v + (size_t)bh * Nn * DHd;

    float acc[4][4] = {};
    for (int k0 = 0; k0 < Nn; k0 += 16) {
        #pragma unroll
        for (int i = 0; i < 4; i++) {
            int l = t + i * 256;
            int mm = l >> 4, kk = l & 15;
            As[kk][mm] = Sb[(size_t)(i0 + mm) * Nn + k0 + kk];
        }
        #pragma unroll
        for (int i = 0; i < 4; i++) {
            int l = t + i * 256;
            int kk = l >> 6, nn = l & 63;
            Vs[kk][nn] = vb[(k0 + kk) * DHd + nn];
        }
        __syncthreads();
        #pragma unroll
        for (int kk = 0; kk < 16; kk++) {
            float4 a4 = *(const float4*)&As[kk][ty * 4];
            float4 b4 = *(const float4*)&Vs[kk][tx * 4];
            float a[4] = {a4.x, a4.y, a4.z, a4.w};
            float b[4] = {b4.x, b4.y, b4.z, b4.w};
            #pragma unroll
            for (int ii = 0; ii < 4; ii++)
                #pragma unroll
                for (int jj = 0; jj < 4; jj++)
                    acc[ii][jj] += a[ii] * b[jj];
        }
        __syncthreads();
    }

    const int b = bh >> 3, h = bh & 7;
    #pragma unroll
    for (int ii = 0; ii < 4; ii++) {
        int i = i0 + ty * 4 + ii;
        #pragma unroll
        for (int jj = 0; jj < 4; jj++) {
            int d = tx * 4 + jj;
            g_ctx[(((size_t)(b * Nn + i) * Hh + h) * DHd) + d] = acc[ii][jj];
        }
    }
}

// ===========================================================================
// Kernel 6: out[8192,512] = ctx[8192,512] @ Wo[512,512] + bo
// ===========================================================================
__global__ void out_gemm_kernel(const float* __restrict__ Wo,
                                const float* __restrict__ bo,
                                float* __restrict__ out) {
    __shared__ __align__(16) float As[16][68];
    __shared__ __align__(16) float Bs[16][64];

    const int n0 = blockIdx.x * 64;
    const int m0 = blockIdx.y * 64;
    const int t  = threadIdx.x;
    const int tx = t & 15, ty = t >> 4;

    float acc[4][4] = {};
    for (int k0 = 0; k0 < 512; k0 += 16) {
        #pragma unroll
        for (int i = 0; i < 4; i++) {
            int l = t + i * 256;
            int mm = l >> 4, kk = l & 15;
            As[kk][mm] = g_ctx[(size_t)(m0 + mm) * INNERi + k0 + kk];
        }
        #pragma unroll
        for (int i = 0; i < 4; i++) {
            int l = t + i * 256;
            int kk = l >> 6, nn = l & 63;
            Bs[kk][nn] = Wo[(k0 + kk) * DIMm + n0 + nn];
        }
        __syncthreads();
        #pragma unroll
        for (int kk = 0; kk < 16; kk++) {
            float4 a4 = *(const float4*)&As[kk][ty * 4];
            float4 b4 = *(const float4*)&Bs[kk][tx * 4];
            float a[4] = {a4.x, a4.y, a4.z, a4.w};
            float b[4] = {b4.x, b4.y, b4.z, b4.w};
            #pragma unroll
            for (int ii = 0; ii < 4; ii++)
                #pragma unroll
                for (int jj = 0; jj < 4; jj++)
                    acc[ii][jj] += a[ii] * b[jj];
        }
        __syncthreads();
    }

    #pragma unroll
    for (int ii = 0; ii < 4; ii++) {
        int m = m0 + ty * 4 + ii;
        #pragma unroll
        for (int jj = 0; jj < 4; jj++) {
            int n = n0 + tx * 4 + jj;
            out[(size_t)m * DIMm + n] = acc[ii][jj] + bo[n];
        }
    }
}

// ===========================================================================
extern "C" void kernel_launch(void* const* d_in, const int* in_sizes, int n_in,
                              void* d_out, int out_size) {
    const float* x   = (const float*)d_in[0];
    const float* Wq  = (const float*)d_in[1];
    const float* Wkv = (const float*)d_in[2];
    const float* Wo  = (const float*)d_in[3];
    const float* bo  = (const float*)d_in[4];
    const float* pos = (const float*)d_in[5];
    float* out = (float*)d_out;

    qkv_kernel     <<<dim3(24, 128), 256>>>(x, Wq, Wkv);
    pos_gemm_kernel<<<dim3(17, 1024), 256>>>(pos);
    score_kernel   <<<dim3(16, 16, 64), 256>>>(0.125f);   // 64^-0.5
    softmax_kernel <<<65536, 256>>>();
    av_kernel      <<<dim3(16, 64), 256>>>();
    out_gemm_kernel<<<dim3(8, 128), 256>>>(Wo, bo, out);
}

// round 4
// speedup vs baseline: 1.4373x; 1.4373x over previous
#include <cuda_runtime.h>
#include <cuda_bf16.h>
#include <cstdint>

#define Nn    1024
#define NPp   1025
#define NPS   1028          // padded row stride for g_P (float2/float4-aligned)
#define BHb   64
#define MXm   8192

// ---------------- device scratch (allocation-free rule: static globals) ----
__device__ uint32_t g_xp  [(size_t)MXm * 512];        // split-packed x
__device__ uint32_t g_wqt [(size_t)512 * 512];        // Wq^T split-packed
__device__ uint32_t g_wkvt[(size_t)1024 * 512];       // Wkv^T split-packed
__device__ uint32_t g_wot [(size_t)512 * 512];        // Wo^T split-packed
__device__ uint32_t g_Tp  [(size_t)1088 * 64];        // pos_table split-packed (padded)
__device__ uint32_t g_qp  [(size_t)BHb * Nn * 64];    // q  [bh][n][d]
__device__ uint32_t g_kp  [(size_t)BHb * Nn * 64];    // k  [bh][n][d]
__device__ uint32_t g_vtp [(size_t)BHb * 64 * Nn];    // v^T [bh][d][n]
__device__ float    g_P   [(size_t)BHb * Nn * NPS];   // pos dots (fp32)
__device__ float    g_S   [(size_t)BHb * Nn * Nn];    // scores / attn (fp32)
__device__ uint32_t g_ctxp[(size_t)MXm * 512];        // context split-packed

// ---------------- smem layout: A/B hi/lo tiles, row stride 144 B -----------
// 144 B = 36 words; 36 ≡ 4 (mod 32) -> fragment loads are bank-conflict-free.
#define STRB  144
#define A_HI  0u
#define A_LO  18432u
#define B_HI  36864u
#define B_LO  46080u
#define SMEM_BYTES 55296

#define LDS32(v, a) asm volatile("ld.shared.b32 %0, [%1];" : "=r"(v) : "r"(a))

static __device__ __forceinline__ uint32_t smem_u32(const void* p) {
    uint32_t a;
    asm("{ .reg .u64 t; cvta.to.shared.u64 t, %1; cvt.u32.u64 %0, t; }" : "=r"(a) : "l"(p));
    return a;
}

static __device__ __forceinline__ uint32_t packsplit(float v) {
    __nv_bfloat16 h = __float2bfloat16(v);
    float r = v - __bfloat162float(h);
    __nv_bfloat16 l = __float2bfloat16(r);
    return ((uint32_t)__bfloat16_as_ushort(l) << 16) | (uint32_t)__bfloat16_as_ushort(h);
}

static __device__ __forceinline__ void mma_bf16(float* d, const uint32_t* a, const uint32_t* b) {
    asm volatile("mma.sync.aligned.m16n8k16.row.col.f32.bf16.bf16.f32 "
                 "{%0,%1,%2,%3}, {%4,%5,%6,%7}, {%8,%9}, {%0,%1,%2,%3};"
                 : "+f"(d[0]), "+f"(d[1]), "+f"(d[2]), "+f"(d[3])
                 : "r"(a[0]), "r"(a[1]), "r"(a[2]), "r"(a[3]), "r"(b[0]), "r"(b[1]));
}

// ---------------- staging: packed [R x 64] tile -> hi/lo smem (128 threads)
template <int R>
static __device__ __forceinline__ void stage_packed(uint8_t* hi, uint8_t* lo,
                                                    const uint32_t* src, int lds, int t) {
    #pragma unroll
    for (int i = 0; i < R * 32 / 128; i++) {
        int idx = t + i * 128;
        int row = idx >> 5, cp = idx & 31;
        uint32_t u0 = src[(size_t)row * lds + 2 * cp];
        uint32_t u1 = src[(size_t)row * lds + 2 * cp + 1];
        uint32_t h2 = (u0 & 0xffffu) | (u1 << 16);
        uint32_t l2 = (u0 >> 16) | (u1 & 0xffff0000u);
        uint32_t off = (uint32_t)row * STRB + (uint32_t)cp * 4;
        *(uint32_t*)(hi + off) = h2;
        *(uint32_t*)(lo + off) = l2;
    }
}

// ---------------- compute one K=64 stage; warp tile 64x32 -------------------
// 3-term split: D += Ah*Bh + Ah*Bl + Al*Bh
static __device__ __forceinline__ void compute_stage(uint32_t sb, int lane, int my, int nx,
                                                     float acc[4][4][4]) {
    const int r = lane >> 2, cc = lane & 3;
    #pragma unroll
    for (int ks = 0; ks < 4; ks++) {
        const uint32_t kb = (uint32_t)ks * 32 + (uint32_t)cc * 4;
        uint32_t ah[4][4], al[4][4];
        #pragma unroll
        for (int mi = 0; mi < 4; mi++) {
            uint32_t ad = sb + (uint32_t)(my * 64 + mi * 16 + r) * STRB + kb;
            LDS32(ah[mi][0], ad + A_HI);
            LDS32(ah[mi][1], ad + A_HI + 8 * STRB);
            LDS32(ah[mi][2], ad + A_HI + 16);
            LDS32(ah[mi][3], ad + A_HI + 8 * STRB + 16);
            LDS32(al[mi][0], ad + A_LO);
            LDS32(al[mi][1], ad + A_LO + 8 * STRB);
            LDS32(al[mi][2], ad + A_LO + 16);
            LDS32(al[mi][3], ad + A_LO + 8 * STRB + 16);
        }
        #pragma unroll
        for (int ni = 0; ni < 4; ni++) {
            uint32_t bd = sb + (uint32_t)(nx * 32 + ni * 8 + r) * STRB + kb;
            uint32_t bh[2], bl[2];
            LDS32(bh[0], bd + B_HI);
            LDS32(bh[1], bd + B_HI + 16);
            LDS32(bl[0], bd + B_LO);
            LDS32(bl[1], bd + B_LO + 16);
            #pragma unroll
            for (int mi = 0; mi < 4; mi++) {
                mma_bf16(acc[mi][ni], ah[mi], bh);
                mma_bf16(acc[mi][ni], ah[mi], bl);
                mma_bf16(acc[mi][ni], al[mi], bh);
            }
        }
    }
}

// ===========================================================================
// Prep kernels (256 threads)
// ===========================================================================
__global__ void pack_x_kernel(const float* __restrict__ x) {
    size_t e = ((size_t)blockIdx.x * 256 + threadIdx.x) * 4;
    float4 v = *(const float4*)(x + e);
    uint4 p;
    p.x = packsplit(v.x); p.y = packsplit(v.y); p.z = packsplit(v.z); p.w = packsplit(v.w);
    *(uint4*)(g_xp + e) = p;
}

__global__ void pack_w_kernel(const float* __restrict__ Wq, const float* __restrict__ Wkv,
                              const float* __restrict__ Wo) {
    size_t e0 = ((size_t)blockIdx.x * 256 + threadIdx.x) * 4;
    #pragma unroll
    for (int cc = 0; cc < 4; cc++) {
        size_t e = e0 + cc;
        if (e < 262144) {                       // Wq^T [512][512]
            int k = (int)(e & 511), n = (int)(e >> 9);
            g_wqt[e] = packsplit(Wq[(size_t)k * 512 + n]);
        } else if (e < 786432) {                // Wkv^T [1024][512]
            size_t l = e - 262144;
            int k = (int)(l & 511), n = (int)(l >> 9);
            g_wkvt[l] = packsplit(Wkv[(size_t)k * 1024 + n]);
        } else {                                // Wo^T [512][512]
            size_t l = e - 786432;
            int k = (int)(l & 511), n = (int)(l >> 9);
            g_wot[l] = packsplit(Wo[(size_t)k * 512 + n]);
        }
    }
}

__global__ void pack_t_kernel(const float* __restrict__ T) {
    size_t e0 = ((size_t)blockIdx.x * 256 + threadIdx.x) * 4;
    #pragma unroll
    for (int cc = 0; cc < 4; cc++) {
        size_t e = e0 + cc;
        int p = (int)(e >> 6), d = (int)(e & 63);
        g_Tp[e] = (p < NPp) ? packsplit(T[(size_t)p * 64 + d]) : 0u;
    }
}

// ===========================================================================
// GEMM 1: QKV.  C[8192,1536] = x @ [Wq|Wkv] -> qp / kp / vtp (split-packed)
// grid(24, 64): n0 = bx*64, m0 = by*128.  128 threads.
// ===========================================================================
__global__ __launch_bounds__(128) void mm_qkv() {
    extern __shared__ uint8_t smem[];
    const uint32_t sb = smem_u32(smem);
    const int t = threadIdx.x, lane = t & 31, wid = t >> 5;
    const int my = wid >> 1, nx = wid & 1;
    const int n0 = blockIdx.x * 64, m0 = blockIdx.y * 128;

    const uint32_t* srcA = g_xp + (size_t)m0 * 512;
    const uint32_t* srcB = (n0 < 512) ? (g_wqt + (size_t)n0 * 512)
                                      : (g_wkvt + (size_t)(n0 - 512) * 512);
    float acc[4][4][4] = {};
    for (int s = 0; s < 8; s++) {
        stage_packed<128>(smem + A_HI, smem + A_LO, srcA + s * 64, 512, t);
        stage_packed<64> (smem + B_HI, smem + B_LO, srcB + s * 64, 512, t);
        __syncthreads();
        compute_stage(sb, lane, my, nx, acc);
        __syncthreads();
    }

    const int b = m0 >> 10, i0 = m0 & 1023;
    const int region = n0 >> 9;                 // 0=q, 1=k, 2=v
    const int h = (n0 >> 6) & 7;
    const int bh = b * 8 + h;
    const int r = lane >> 2, cc = lane & 3;

    if (region == 2) {
        // write v transposed: vtp[bh][d][i]
        #pragma unroll
        for (int mi = 0; mi < 4; mi++)
        #pragma unroll
        for (int ni = 0; ni < 4; ni++)
        #pragma unroll
        for (int g = 0; g < 2; g++) {
            int i = i0 + my * 64 + mi * 16 + r + g * 8;
            int d = nx * 32 + ni * 8 + cc * 2;
            g_vtp[((size_t)bh * 64 + d)     * 1024 + i] = packsplit(acc[mi][ni][2 * g]);
            g_vtp[((size_t)bh * 64 + d + 1) * 1024 + i] = packsplit(acc[mi][ni][2 * g + 1]);
        }
    } else {
        uint32_t* dst = (region == 0 ? g_qp : g_kp) + ((size_t)bh * 1024 + i0) * 64;
        #pragma unroll
        for (int mi = 0; mi < 4; mi++)
        #pragma unroll
        for (int ni = 0; ni < 4; ni++)
        #pragma unroll
        for (int g = 0; g < 2; g++) {
            int il = my * 64 + mi * 16 + r + g * 8;
            int d  = nx * 32 + ni * 8 + cc * 2;
            uint2 pk;
            pk.x = packsplit(acc[mi][ni][2 * g]);
            pk.y = packsplit(acc[mi][ni][2 * g + 1]);
            *(uint2*)&dst[(size_t)il * 64 + d] = pk;
        }
    }
}

// ===========================================================================
// GEMM 2: P[m, p] = q[m] . pos_table[p].  grid(17, 512): p0 = bx*64, m0 = by*128
// ===========================================================================
__global__ __launch_bounds__(128) void mm_pos() {
    extern __shared__ uint8_t smem[];
    const uint32_t sb = smem_u32(smem);
    const int t = threadIdx.x, lane = t & 31, wid = t >> 5;
    const int my = wid >> 1, nx = wid & 1;
    const int p0 = blockIdx.x * 64, m0 = blockIdx.y * 128;

    float acc[4][4][4] = {};
    stage_packed<128>(smem + A_HI, smem + A_LO, g_qp + (size_t)m0 * 64, 64, t);
    stage_packed<64> (smem + B_HI, smem + B_LO, g_Tp + (size_t)p0 * 64, 64, t);
    __syncthreads();
    compute_stage(sb, lane, my, nx, acc);

    const int r = lane >> 2, cc = lane & 3;
    #pragma unroll
    for (int mi = 0; mi < 4; mi++)
    #pragma unroll
    for (int ni = 0; ni < 4; ni++)
    #pragma unroll
    for (int g = 0; g < 2; g++) {
        int m = m0 + my * 64 + mi * 16 + r + g * 8;
        int p = p0 + nx * 32 + ni * 8 + cc * 2;
        float v0 = acc[mi][ni][2 * g], v1 = acc[mi][ni][2 * g + 1];
        if (p + 1 < NPp) {
            float2 v = make_float2(v0, v1);
            *(float2*)&g_P[(size_t)m * NPS + p] = v;
        } else if (p < NPp) {
            g_P[(size_t)m * NPS + p] = v0;
        }
    }
}

// ===========================================================================
// GEMM 3: S[bh,i,j] = scale*(q_i.k_j + P[bh,i,clip(i-j)+512])
// grid(16, 8, 64): j0 = bx*64, i0 = by*128, bh = bz
// ===========================================================================
__global__ __launch_bounds__(128) void mm_score() {
    extern __shared__ uint8_t smem[];
    const uint32_t sb = smem_u32(smem);
    const int t = threadIdx.x, lane = t & 31, wid = t >> 5;
    const int my = wid >> 1, nx = wid & 1;
    const int j0 = blockIdx.x * 64, i0 = blockIdx.y * 128, bh = blockIdx.z;

    float acc[4][4][4] = {};
    stage_packed<128>(smem + A_HI, smem + A_LO, g_qp + ((size_t)bh * 1024 + i0) * 64, 64, t);
    stage_packed<64> (smem + B_HI, smem + B_LO, g_kp + ((size_t)bh * 1024 + j0) * 64, 64, t);
    __syncthreads();
    compute_stage(sb, lane, my, nx, acc);

    const float* Pb = g_P + ((size_t)bh * 1024 + i0) * NPS;
    float* Sb = g_S + ((size_t)bh * 1024 + i0) * 1024 + j0;
    const int r = lane >> 2, cc = lane & 3;
    #pragma unroll
    for (int mi = 0; mi < 4; mi++)
    #pragma unroll
    for (int ni = 0; ni < 4; ni++)
    #pragma unroll
    for (int g = 0; g < 2; g++) {
        int il = my * 64 + mi * 16 + r + g * 8;
        int jl = nx * 32 + ni * 8 + cc * 2;
        int i = i0 + il, j = j0 + jl;
        int d0 = max(-512, min(512, i - j));
        int d1 = max(-512, min(512, i - j - 1));
        float pv0 = Pb[(size_t)il * NPS + d0 + 512];
        float pv1 = Pb[(size_t)il * NPS + d1 + 512];
        float2 v;
        v.x = 0.125f * (acc[mi][ni][2 * g]     + pv0);
        v.y = 0.125f * (acc[mi][ni][2 * g + 1] + pv1);
        *(float2*)&Sb[(size_t)il * 1024 + jl] = v;
    }
}

// ===========================================================================
// Softmax (memory-bound, unchanged)
// ===========================================================================
__global__ void softmax_kernel() {
    __shared__ float redm[8];
    __shared__ float reds[8];
    const size_t row = blockIdx.x;
    float* S = g_S + row * (size_t)Nn;
    const int t = threadIdx.x;
    const int lane = t & 31, warp = t >> 5;

    float4 v = *(float4*)(S + t * 4);
    float m = fmaxf(fmaxf(v.x, v.y), fmaxf(v.z, v.w));
    #pragma unroll
    for (int o = 16; o; o >>= 1) m = fmaxf(m, __shfl_xor_sync(0xffffffffu, m, o));
    if (lane == 0) redm[warp] = m;
    __syncthreads();
    float rowmax = redm[0];
    #pragma unroll
    for (int i = 1; i < 8; i++) rowmax = fmaxf(rowmax, redm[i]);

    float4 e;
    e.x = __expf(v.x - rowmax); e.y = __expf(v.y - rowmax);
    e.z = __expf(v.z - rowmax); e.w = __expf(v.w - rowmax);
    float s = e.x + e.y + e.z + e.w;
    #pragma unroll
    for (int o = 16; o; o >>= 1) s += __shfl_xor_sync(0xffffffffu, s, o);
    if (lane == 0) reds[warp] = s;
    __syncthreads();
    float tot = 0.0f;
    #pragma unroll
    for (int i = 0; i < 8; i++) tot += reds[i];
    float inv = 1.0f / tot;
    e.x *= inv; e.y *= inv; e.z *= inv; e.w *= inv;
    *(float4*)(S + t * 4) = e;
}

// ===========================================================================
// GEMM 4: ctx = attn @ v.  grid(8, 64): i0 = bx*128, bh = by
// A = split(S fp32) on the fly, B = vtp rows ([d][j] = [n][k]).
// ===========================================================================
__global__ __launch_bounds__(128) void mm_av() {
    extern __shared__ uint8_t smem[];
    const uint32_t sb = smem_u32(smem);
    const int t = threadIdx.x, lane = t & 31, wid = t >> 5;
    const int my = wid >> 1, nx = wid & 1;
    const int i0 = blockIdx.x * 128, bh = blockIdx.y;

    const float* Sa = g_S + ((size_t)bh * 1024 + i0) * 1024;
    const uint32_t* Vb = g_vtp + (size_t)bh * 64 * 1024;

    float acc[4][4][4] = {};
    for (int s = 0; s < 16; s++) {
        const int k0 = s * 64;
        #pragma unroll
        for (int i = 0; i < 32; i++) {
            int idx = t + i * 128;
            int row = idx >> 5, cp = idx & 31;
            float2 v = *(const float2*)&Sa[(size_t)row * 1024 + k0 + 2 * cp];
            __nv_bfloat16 ha = __float2bfloat16(v.x), hb = __float2bfloat16(v.y);
            __nv_bfloat16 la = __float2bfloat16(v.x - __bfloat162float(ha));
            __nv_bfloat16 lb = __float2bfloat16(v.y - __bfloat162float(hb));
            uint32_t h2 = ((uint32_t)__bfloat16_as_ushort(hb) << 16) | __bfloat16_as_ushort(ha);
            uint32_t l2 = ((uint32_t)__bfloat16_as_ushort(lb) << 16) | __bfloat16_as_ushort(la);
            uint32_t off = (uint32_t)row * STRB + (uint32_t)cp * 4;
            *(uint32_t*)(smem + A_HI + off) = h2;
            *(uint32_t*)(smem + A_LO + off) = l2;
        }
        stage_packed<64>(smem + B_HI, smem + B_LO, Vb + k0, 1024, t);
        __syncthreads();
        compute_stage(sb, lane, my, nx, acc);
        __syncthreads();
    }

    const int b = bh >> 3, h = bh & 7;
    uint32_t* dst = g_ctxp + ((size_t)(b * 1024 + i0)) * 512 + h * 64;
    const int r = lane >> 2, cc = lane & 3;
    #pragma unroll
    for (int mi = 0; mi < 4; mi++)
    #pragma unroll
    for (int ni = 0; ni < 4; ni++)
    #pragma unroll
    for (int g = 0; g < 2; g++) {
        int il = my * 64 + mi * 16 + r + g * 8;
        int d  = nx * 32 + ni * 8 + cc * 2;
        uint2 pk;
        pk.x = packsplit(acc[mi][ni][2 * g]);
        pk.y = packsplit(acc[mi][ni][2 * g + 1]);
        *(uint2*)&dst[(size_t)il * 512 + d] = pk;
    }
}

// ===========================================================================
// GEMM 5: out = ctx @ Wo + bo.  grid(8, 64): n0 = bx*64, m0 = by*128
// ===========================================================================
__global__ __launch_bounds__(128) void mm_out(const float* __restrict__ bo,
                                              float* __restrict__ out) {
    extern __shared__ uint8_t smem[];
    const uint32_t sb = smem_u32(smem);
    const int t = threadIdx.x, lane = t & 31, wid = t >> 5;
    const int my = wid >> 1, nx = wid & 1;
    const int n0 = blockIdx.x * 64, m0 = blockIdx.y * 128;

    const uint32_t* srcA = g_ctxp + (size_t)m0 * 512;
    const uint32_t* srcB = g_wot + (size_t)n0 * 512;
    float acc[4][4][4] = {};
    for (int s = 0; s < 8; s++) {
        stage_packed<128>(smem + A_HI, smem + A_LO, srcA + s * 64, 512, t);
        stage_packed<64> (smem + B_HI, smem + B_LO, srcB + s * 64, 512, t);
        __syncthreads();
        compute_stage(sb, lane, my, nx, acc);
        __syncthreads();
    }

    const int r = lane >> 2, cc = lane & 3;
    #pragma unroll
    for (int mi = 0; mi < 4; mi++)
    #pragma unroll
    for (int ni = 0; ni < 4; ni++)
    #pragma unroll
    for (int g = 0; g < 2; g++) {
        int m = m0 + my * 64 + mi * 16 + r + g * 8;
        int n = n0 + nx * 32 + ni * 8 + cc * 2;
        float2 v;
        v.x = acc[mi][ni][2 * g]     + bo[n];
        v.y = acc[mi][ni][2 * g + 1] + bo[n + 1];
        *(float2*)&out[(size_t)m * 512 + n] = v;
    }
}

// ===========================================================================
extern "C" void kernel_launch(void* const* d_in, const int* in_sizes, int n_in,
                              void* d_out, int out_size) {
    const float* x   = (const float*)d_in[0];
    const float* Wq  = (const float*)d_in[1];
    const float* Wkv = (const float*)d_in[2];
    const float* Wo  = (const float*)d_in[3];
    const float* bo  = (const float*)d_in[4];
    const float* pos = (const float*)d_in[5];
    float* out = (float*)d_out;

    cudaFuncSetAttribute(mm_qkv,   cudaFuncAttributeMaxDynamicSharedMemorySize, SMEM_BYTES);
    cudaFuncSetAttribute(mm_pos,   cudaFuncAttributeMaxDynamicSharedMemorySize, SMEM_BYTES);
    cudaFuncSetAttribute(mm_score, cudaFuncAttributeMaxDynamicSharedMemorySize, SMEM_BYTES);
    cudaFuncSetAttribute(mm_av,    cudaFuncAttributeMaxDynamicSharedMemorySize, SMEM_BYTES);
    cudaFuncSetAttribute(mm_out,   cudaFuncAttributeMaxDynamicSharedMemorySize, SMEM_BYTES);

    pack_x_kernel<<<4096, 256>>>(x);
    pack_w_kernel<<<1024, 256>>>(Wq, Wkv, Wo);
    pack_t_kernel<<<68, 256>>>(pos);

    mm_qkv  <<<dim3(24, 64),    128, SMEM_BYTES>>>();
    mm_pos  <<<dim3(17, 512),   128, SMEM_BYTES>>>();
    mm_score<<<dim3(16, 8, 64), 128, SMEM_BYTES>>>();
    softmax_kernel<<<65536, 256>>>();
    mm_av   <<<dim3(8, 64),     128, SMEM_BYTES>>>();
    mm_out  <<<dim3(8, 64),     128, SMEM_BYTES>>>(bo, out);
}

// round 5
// speedup vs baseline: 1.8419x; 1.2815x over previous
#include <cuda_runtime.h>
#include <cuda_bf16.h>
#include <cstdint>

#define Nn    1024
#define NPp   1025
#define NPS   1028          // padded row stride for g_P
#define BHb   64
#define MXm   8192

typedef __nv_bfloat16 bf16;

// ---------------- device scratch (hi/lo split bf16 arrays) -----------------
__device__ bf16  g_xh [(size_t)MXm * 512],      g_xl [(size_t)MXm * 512];
__device__ bf16  g_wqh[(size_t)512 * 512],      g_wql[(size_t)512 * 512];    // [n][k]
__device__ bf16  g_wkvh[(size_t)1024 * 512],    g_wkvl[(size_t)1024 * 512];  // [n][k]
__device__ bf16  g_woh[(size_t)512 * 512],      g_wol[(size_t)512 * 512];    // [n][k]
__device__ bf16  g_th [(size_t)1088 * 64],      g_tl [(size_t)1088 * 64];    // [p][d]
__device__ bf16  g_qh [(size_t)BHb * Nn * 64],  g_ql [(size_t)BHb * Nn * 64];
__device__ bf16  g_kh [(size_t)BHb * Nn * 64],  g_kl [(size_t)BHb * Nn * 64];
__device__ bf16  g_vth[(size_t)BHb * 64 * Nn],  g_vtl[(size_t)BHb * 64 * Nn]; // [bh][d][j]
__device__ bf16  g_sah[(size_t)BHb * Nn * Nn],  g_sal[(size_t)BHb * Nn * Nn]; // attn split
__device__ bf16  g_ch [(size_t)MXm * 512],      g_cl [(size_t)MXm * 512];     // ctx [b,n][h*d]
__device__ float g_P  [(size_t)BHb * Nn * NPS];
__device__ float g_S  [(size_t)BHb * Nn * Nn];

// ---------------- smem: A/B hi/lo tiles, row stride 144 B ------------------
#define STRB  144
#define A_HI  0u
#define A_LO  18432u
#define B_HI  36864u
#define B_LO  46080u
#define BUFB  55296u
#define SMEM_1 55296
#define SMEM_2 110592

#define LDS32(v, a) asm volatile("ld.shared.b32 %0, [%1];" : "=r"(v) : "r"(a))
#define CP16(d, s)  asm volatile("cp.async.ca.shared.global [%0], [%1], 16;" :: "r"(d), "l"(s))
#define CP_COMMIT() asm volatile("cp.async.commit_group;" ::: "memory")
#define CP_WAIT(n)  asm volatile("cp.async.wait_group %0;" :: "n"(n) : "memory")

static __device__ __forceinline__ uint32_t smem_u32(const void* p) {
    uint32_t a;
    asm("{ .reg .u64 t; cvta.to.shared.u64 t, %1; cvt.u32.u64 %0, t; }" : "=r"(a) : "l"(p));
    return a;
}

static __device__ __forceinline__ void split1(float v, bf16& h, bf16& l) {
    h = __float2bfloat16(v);
    l = __float2bfloat16(v - __bfloat162float(h));
}
static __device__ __forceinline__ void split2(float v0, float v1, uint32_t& h2, uint32_t& l2) {
    bf16 h0, l0, h1, l1;
    split1(v0, h0, l0); split1(v1, h1, l1);
    h2 = (uint32_t)__bfloat16_as_ushort(h0) | ((uint32_t)__bfloat16_as_ushort(h1) << 16);
    l2 = (uint32_t)__bfloat16_as_ushort(l0) | ((uint32_t)__bfloat16_as_ushort(l1) << 16);
}

static __device__ __forceinline__ void mma_bf16(float* d, const uint32_t* a, const uint32_t* b) {
    asm volatile("mma.sync.aligned.m16n8k16.row.col.f32.bf16.bf16.f32 "
                 "{%0,%1,%2,%3}, {%4,%5,%6,%7}, {%8,%9}, {%0,%1,%2,%3};"
                 : "+f"(d[0]), "+f"(d[1]), "+f"(d[2]), "+f"(d[3])
                 : "r"(a[0]), "r"(a[1]), "r"(a[2]), "r"(a[3]), "r"(b[0]), "r"(b[1]));
}

// ---------------- cp.async staging: [R x 64] bf16 tile ---------------------
template <int R>
static __device__ __forceinline__ void stage_cp(uint32_t sdst, const bf16* src, int lds, int t) {
    #pragma unroll
    for (int i = 0; i < R * 8 / 128; i++) {
        int idx = t + i * 128;
        int row = idx >> 3, ch = idx & 7;
        CP16(sdst + (uint32_t)row * STRB + (uint32_t)ch * 16,
             src + (size_t)row * lds + ch * 8);
    }
}

// stage one full K=64 stage (A hi/lo R=128, B hi/lo R=64) into buffer
static __device__ __forceinline__ void stage_all(uint32_t sb,
                                                 const bf16* ah, const bf16* al, int ldsa,
                                                 const bf16* bh, const bf16* bl, int ldsb, int t) {
    stage_cp<128>(sb + A_HI, ah, ldsa, t);
    stage_cp<128>(sb + A_LO, al, ldsa, t);
    stage_cp<64> (sb + B_HI, bh, ldsb, t);
    stage_cp<64> (sb + B_LO, bl, ldsb, t);
    CP_COMMIT();
}

// ---------------- compute one K=64 stage; warp tile 64x32 ------------------
// term-major order: 16 independent MMAs between accumulator reuses
static __device__ __forceinline__ void compute_stage(uint32_t sb, int lane, int my, int nx,
                                                     float acc[4][4][4]) {
    const int r = lane >> 2, cc = lane & 3;
    #pragma unroll
    for (int ks = 0; ks < 4; ks++) {
        const uint32_t kb = (uint32_t)ks * 32 + (uint32_t)cc * 4;
        uint32_t ah[4][4], al[4][4], bh[4][2], bl[4][2];
        #pragma unroll
        for (int mi = 0; mi < 4; mi++) {
            uint32_t ad = sb + (uint32_t)(my * 64 + mi * 16 + r) * STRB + kb;
            LDS32(ah[mi][0], ad + A_HI);
            LDS32(ah[mi][1], ad + A_HI + 8 * STRB);
            LDS32(ah[mi][2], ad + A_HI + 16);
            LDS32(ah[mi][3], ad + A_HI + 8 * STRB + 16);
            LDS32(al[mi][0], ad + A_LO);
            LDS32(al[mi][1], ad + A_LO + 8 * STRB);
            LDS32(al[mi][2], ad + A_LO + 16);
            LDS32(al[mi][3], ad + A_LO + 8 * STRB + 16);
        }
        #pragma unroll
        for (int ni = 0; ni < 4; ni++) {
            uint32_t bd = sb + (uint32_t)(nx * 32 + ni * 8 + r) * STRB + kb;
            LDS32(bh[ni][0], bd + B_HI);
            LDS32(bh[ni][1], bd + B_HI + 16);
            LDS32(bl[ni][0], bd + B_LO);
            LDS32(bl[ni][1], bd + B_LO + 16);
        }
        #pragma unroll
        for (int ni = 0; ni < 4; ni++)
            #pragma unroll
            for (int mi = 0; mi < 4; mi++)
                mma_bf16(acc[mi][ni], ah[mi], bh[ni]);
        #pragma unroll
        for (int ni = 0; ni < 4; ni++)
            #pragma unroll
            for (int mi = 0; mi < 4; mi++)
                mma_bf16(acc[mi][ni], ah[mi], bl[ni]);
        #pragma unroll
        for (int ni = 0; ni < 4; ni++)
            #pragma unroll
            for (int mi = 0; mi < 4; mi++)
                mma_bf16(acc[mi][ni], al[mi], bh[ni]);
    }
}

// ===========================================================================
// Prep kernels
// ===========================================================================
__global__ void pack_x_kernel(const float* __restrict__ x) {
    size_t e = ((size_t)blockIdx.x * 256 + threadIdx.x) * 4;
    float4 v = *(const float4*)(x + e);
    uint32_t h0, l0, h1, l1;
    split2(v.x, v.y, h0, l0);
    split2(v.z, v.w, h1, l1);
    *(uint2*)&g_xh[e] = make_uint2(h0, h1);
    *(uint2*)&g_xl[e] = make_uint2(l0, l1);
}

__global__ void pack_w_kernel(const float* __restrict__ Wq, const float* __restrict__ Wkv,
                              const float* __restrict__ Wo) {
    size_t e0 = ((size_t)blockIdx.x * 256 + threadIdx.x) * 4;
    #pragma unroll
    for (int cc = 0; cc < 4; cc++) {
        size_t e = e0 + cc;
        bf16 h, l;
        if (e < 262144) {
            int k = (int)(e & 511), n = (int)(e >> 9);
            split1(Wq[(size_t)k * 512 + n], h, l);
            g_wqh[e] = h; g_wql[e] = l;
        } else if (e < 786432) {
            size_t m = e - 262144;
            int k = (int)(m & 511), n = (int)(m >> 9);
            split1(Wkv[(size_t)k * 1024 + n], h, l);
            g_wkvh[m] = h; g_wkvl[m] = l;
        } else {
            size_t m = e - 786432;
            int k = (int)(m & 511), n = (int)(m >> 9);
            split1(Wo[(size_t)k * 512 + n], h, l);
            g_woh[m] = h; g_wol[m] = l;
        }
    }
}

__global__ void pack_t_kernel(const float* __restrict__ T) {
    size_t e0 = ((size_t)blockIdx.x * 256 + threadIdx.x) * 4;
    #pragma unroll
    for (int cc = 0; cc < 4; cc++) {
        size_t e = e0 + cc;
        int p = (int)(e >> 6), d = (int)(e & 63);
        bf16 h = __float2bfloat16(0.f), l = h;
        if (p < NPp) split1(T[(size_t)p * 64 + d], h, l);
        g_th[e] = h; g_tl[e] = l;
    }
}

// ===========================================================================
// GEMM 1: QKV. grid(24, 64): n0 = bx*64, m0 = by*128.  8 K-stages, pipelined.
// ===========================================================================
__global__ __launch_bounds__(128) void mm_qkv() {
    extern __shared__ uint8_t smem[];
    const uint32_t sb = smem_u32(smem);
    const int t = threadIdx.x, lane = t & 31, wid = t >> 5;
    const int my = wid >> 1, nx = wid & 1;
    const int n0 = blockIdx.x * 64, m0 = blockIdx.y * 128;

    const bf16* ah = g_xh + (size_t)m0 * 512;
    const bf16* al = g_xl + (size_t)m0 * 512;
    const bf16* bh = (n0 < 512) ? (g_wqh + (size_t)n0 * 512) : (g_wkvh + (size_t)(n0 - 512) * 512);
    const bf16* bl = (n0 < 512) ? (g_wql + (size_t)n0 * 512) : (g_wkvl + (size_t)(n0 - 512) * 512);

    float acc[4][4][4] = {};
    stage_all(sb, ah, al, 512, bh, bl, 512, t);
    for (int s = 0; s < 8; s++) {
        if (s + 1 < 8) {
            stage_all(sb + ((s + 1) & 1) * BUFB, ah + (s + 1) * 64, al + (s + 1) * 64, 512,
                      bh + (s + 1) * 64, bl + (s + 1) * 64, 512, t);
            CP_WAIT(1);
        } else {
            CP_WAIT(0);
        }
        __syncthreads();
        compute_stage(sb + (s & 1) * BUFB, lane, my, nx, acc);
        __syncthreads();
    }

    const int b = m0 >> 10, i0 = m0 & 1023;
    const int region = n0 >> 9;
    const int h = (n0 >> 6) & 7;
    const int bh_idx = b * 8 + h;
    const int r = lane >> 2, cc = lane & 3;

    if (region == 2) {
        #pragma unroll
        for (int mi = 0; mi < 4; mi++)
        #pragma unroll
        for (int ni = 0; ni < 4; ni++)
        #pragma unroll
        for (int g = 0; g < 2; g++) {
            int i = i0 + my * 64 + mi * 16 + r + g * 8;
            int d = nx * 32 + ni * 8 + cc * 2;
            bf16 h0, l0, h1, l1;
            split1(acc[mi][ni][2 * g],     h0, l0);
            split1(acc[mi][ni][2 * g + 1], h1, l1);
            g_vth[((size_t)bh_idx * 64 + d)     * 1024 + i] = h0;
            g_vtl[((size_t)bh_idx * 64 + d)     * 1024 + i] = l0;
            g_vth[((size_t)bh_idx * 64 + d + 1) * 1024 + i] = h1;
            g_vtl[((size_t)bh_idx * 64 + d + 1) * 1024 + i] = l1;
        }
    } else {
        bf16* dh = (region == 0 ? g_qh : g_kh) + ((size_t)bh_idx * 1024 + i0) * 64;
        bf16* dl = (region == 0 ? g_ql : g_kl) + ((size_t)bh_idx * 1024 + i0) * 64;
        #pragma unroll
        for (int mi = 0; mi < 4; mi++)
        #pragma unroll
        for (int ni = 0; ni < 4; ni++)
        #pragma unroll
        for (int g = 0; g < 2; g++) {
            int il = my * 64 + mi * 16 + r + g * 8;
            int d  = nx * 32 + ni * 8 + cc * 2;
            uint32_t h2, l2;
            split2(acc[mi][ni][2 * g], acc[mi][ni][2 * g + 1], h2, l2);
            *(uint32_t*)&dh[(size_t)il * 64 + d] = h2;
            *(uint32_t*)&dl[(size_t)il * 64 + d] = l2;
        }
    }
}

// ===========================================================================
// GEMM 2: P = q . pos_table^T.  grid(17, 512): p0 = bx*64, m0 = by*128
// ===========================================================================
__global__ __launch_bounds__(128) void mm_pos() {
    extern __shared__ uint8_t smem[];
    const uint32_t sb = smem_u32(smem);
    const int t = threadIdx.x, lane = t & 31, wid = t >> 5;
    const int my = wid >> 1, nx = wid & 1;
    const int p0 = blockIdx.x * 64, m0 = blockIdx.y * 128;

    float acc[4][4][4] = {};
    stage_all(sb, g_qh + (size_t)m0 * 64, g_ql + (size_t)m0 * 64, 64,
              g_th + (size_t)p0 * 64, g_tl + (size_t)p0 * 64, 64, t);
    CP_WAIT(0);
    __syncthreads();
    compute_stage(sb, lane, my, nx, acc);

    const int r = lane >> 2, cc = lane & 3;
    #pragma unroll
    for (int mi = 0; mi < 4; mi++)
    #pragma unroll
    for (int ni = 0; ni < 4; ni++)
    #pragma unroll
    for (int g = 0; g < 2; g++) {
        int m = m0 + my * 64 + mi * 16 + r + g * 8;
        int p = p0 + nx * 32 + ni * 8 + cc * 2;
        if (p + 1 < NPp) {
            *(float2*)&g_P[(size_t)m * NPS + p] =
                make_float2(acc[mi][ni][2 * g], acc[mi][ni][2 * g + 1]);
        } else if (p < NPp) {
            g_P[(size_t)m * NPS + p] = acc[mi][ni][2 * g];
        }
    }
}

// ===========================================================================
// GEMM 3: S = scale*(q.k^T + P gather).  grid(16, 8, 64)
// ===========================================================================
__global__ __launch_bounds__(128) void mm_score() {
    extern __shared__ uint8_t smem[];
    const uint32_t sb = smem_u32(smem);
    const int t = threadIdx.x, lane = t & 31, wid = t >> 5;
    const int my = wid >> 1, nx = wid & 1;
    const int j0 = blockIdx.x * 64, i0 = blockIdx.y * 128, bh = blockIdx.z;

    float acc[4][4][4] = {};
    stage_all(sb, g_qh + ((size_t)bh * 1024 + i0) * 64, g_ql + ((size_t)bh * 1024 + i0) * 64, 64,
              g_kh + ((size_t)bh * 1024 + j0) * 64, g_kl + ((size_t)bh * 1024 + j0) * 64, 64, t);
    CP_WAIT(0);
    __syncthreads();
    compute_stage(sb, lane, my, nx, acc);

    const float* Pb = g_P + ((size_t)bh * 1024 + i0) * NPS;
    float* Sb = g_S + ((size_t)bh * 1024 + i0) * 1024 + j0;
    const int r = lane >> 2, cc = lane & 3;
    #pragma unroll
    for (int mi = 0; mi < 4; mi++)
    #pragma unroll
    for (int ni = 0; ni < 4; ni++)
    #pragma unroll
    for (int g = 0; g < 2; g++) {
        int il = my * 64 + mi * 16 + r + g * 8;
        int jl = nx * 32 + ni * 8 + cc * 2;
        int i = i0 + il, j = j0 + jl;
        int d0 = max(-512, min(512, i - j));
        int d1 = max(-512, min(512, i - j - 1));
        float pv0 = Pb[(size_t)il * NPS + d0 + 512];
        float pv1 = Pb[(size_t)il * NPS + d1 + 512];
        float2 v;
        v.x = 0.125f * (acc[mi][ni][2 * g]     + pv0);
        v.y = 0.125f * (acc[mi][ni][2 * g + 1] + pv1);
        *(float2*)&Sb[(size_t)il * 1024 + jl] = v;
    }
}

// ===========================================================================
// Softmax: reads fp32 S, writes hi/lo split attn
// ===========================================================================
__global__ void softmax_kernel() {
    __shared__ float redm[8];
    __shared__ float reds[8];
    const size_t row = blockIdx.x;
    const float* S = g_S + row * (size_t)Nn;
    const int t = threadIdx.x;
    const int lane = t & 31, warp = t >> 5;

    float4 v = *(const float4*)(S + t * 4);
    float m = fmaxf(fmaxf(v.x, v.y), fmaxf(v.z, v.w));
    #pragma unroll
    for (int o = 16; o; o >>= 1) m = fmaxf(m, __shfl_xor_sync(0xffffffffu, m, o));
    if (lane == 0) redm[warp] = m;
    __syncthreads();
    float rowmax = redm[0];
    #pragma unroll
    for (int i = 1; i < 8; i++) rowmax = fmaxf(rowmax, redm[i]);

    float4 e;
    e.x = __expf(v.x - rowmax); e.y = __expf(v.y - rowmax);
    e.z = __expf(v.z - rowmax); e.w = __expf(v.w - rowmax);
    float s = e.x + e.y + e.z + e.w;
    #pragma unroll
    for (int o = 16; o; o >>= 1) s += __shfl_xor_sync(0xffffffffu, s, o);
    if (lane == 0) reds[warp] = s;
    __syncthreads();
    float tot = 0.0f;
    #pragma unroll
    for (int i = 0; i < 8; i++) tot += reds[i];
    float inv = 1.0f / tot;
    e.x *= inv; e.y *= inv; e.z *= inv; e.w *= inv;

    uint32_t h0, l0, h1, l1;
    split2(e.x, e.y, h0, l0);
    split2(e.z, e.w, h1, l1);
    *(uint2*)&g_sah[row * Nn + t * 4] = make_uint2(h0, h1);
    *(uint2*)&g_sal[row * Nn + t * 4] = make_uint2(l0, l1);
}

// ===========================================================================
// GEMM 4: ctx = attn @ v.  grid(8, 64): i0 = bx*128, bh = by.  16 stages.
// ===========================================================================
__global__ __launch_bounds__(128) void mm_av() {
    extern __shared__ uint8_t smem[];
    const uint32_t sb = smem_u32(smem);
    const int t = threadIdx.x, lane = t & 31, wid = t >> 5;
    const int my = wid >> 1, nx = wid & 1;
    const int i0 = blockIdx.x * 128, bh = blockIdx.y;

    const bf16* ah = g_sah + ((size_t)bh * 1024 + i0) * 1024;
    const bf16* al = g_sal + ((size_t)bh * 1024 + i0) * 1024;
    const bf16* vh = g_vth + (size_t)bh * 64 * 1024;
    const bf16* vl = g_vtl + (size_t)bh * 64 * 1024;

    float acc[4][4][4] = {};
    stage_all(sb, ah, al, 1024, vh, vl, 1024, t);
    for (int s = 0; s < 16; s++) {
        if (s + 1 < 16) {
            stage_all(sb + ((s + 1) & 1) * BUFB, ah + (s + 1) * 64, al + (s + 1) * 64, 1024,
                      vh + (s + 1) * 64, vl + (s + 1) * 64, 1024, t);
            CP_WAIT(1);
        } else {
            CP_WAIT(0);
        }
        __syncthreads();
        compute_stage(sb + (s & 1) * BUFB, lane, my, nx, acc);
        __syncthreads();
    }

    const int b = bh >> 3, h = bh & 7;
    bf16* dh = g_ch + ((size_t)(b * 1024 + i0)) * 512 + h * 64;
    bf16* dl = g_cl + ((size_t)(b * 1024 + i0)) * 512 + h * 64;
    const int r = lane >> 2, cc = lane & 3;
    #pragma unroll
    for (int mi = 0; mi < 4; mi++)
    #pragma unroll
    for (int ni = 0; ni < 4; ni++)
    #pragma unroll
    for (int g = 0; g < 2; g++) {
        int il = my * 64 + mi * 16 + r + g * 8;
        int d  = nx * 32 + ni * 8 + cc * 2;
        uint32_t h2, l2;
        split2(acc[mi][ni][2 * g], acc[mi][ni][2 * g + 1], h2, l2);
        *(uint32_t*)&dh[(size_t)il * 512 + d] = h2;
        *(uint32_t*)&dl[(size_t)il * 512 + d] = l2;
    }
}

// ===========================================================================
// GEMM 5: out = ctx @ Wo + bo.  grid(8, 64).  8 stages.
// ===========================================================================
__global__ __launch_bounds__(128) void mm_out(const float* __restrict__ bo,
                                              float* __restrict__ out) {
    extern __shared__ uint8_t smem[];
    const uint32_t sb = smem_u32(smem);
    const int t = threadIdx.x, lane = t & 31, wid = t >> 5;
    const int my = wid >> 1, nx = wid & 1;
    const int n0 = blockIdx.x * 64, m0 = blockIdx.y * 128;

    const bf16* ah = g_ch + (size_t)m0 * 512;
    const bf16* al = g_cl + (size_t)m0 * 512;
    const bf16* bhp = g_woh + (size_t)n0 * 512;
    const bf16* blp = g_wol + (size_t)n0 * 512;

    float acc[4][4][4] = {};
    stage_all(sb, ah, al, 512, bhp, blp, 512, t);
    for (int s = 0; s < 8; s++) {
        if (s + 1 < 8) {
            stage_all(sb + ((s + 1) & 1) * BUFB, ah + (s + 1) * 64, al + (s + 1) * 64, 512,
                      bhp + (s + 1) * 64, blp + (s + 1) * 64, 512, t);
            CP_WAIT(1);
        } else {
            CP_WAIT(0);
        }
        __syncthreads();
        compute_stage(sb + (s & 1) * BUFB, lane, my, nx, acc);
        __syncthreads();
    }

    const int r = lane >> 2, cc = lane & 3;
    #pragma unroll
    for (int mi = 0; mi < 4; mi++)
    #pragma unroll
    for (int ni = 0; ni < 4; ni++)
    #pragma unroll
    for (int g = 0; g < 2; g++) {
        int m = m0 + my * 64 + mi * 16 + r + g * 8;
        int n = n0 + nx * 32 + ni * 8 + cc * 2;
        float2 v;
        v.x = acc[mi][ni][2 * g]     + bo[n];
        v.y = acc[mi][ni][2 * g + 1] + bo[n + 1];
        *(float2*)&out[(size_t)m * 512 + n] = v;
    }
}

// ===========================================================================
extern "C" void kernel_launch(void* const* d_in, const int* in_sizes, int n_in,
                              void* d_out, int out_size) {
    const float* x   = (const float*)d_in[0];
    const float* Wq  = (const float*)d_in[1];
    const float* Wkv = (const float*)d_in[2];
    const float* Wo  = (const float*)d_in[3];
    const float* bo  = (const float*)d_in[4];
    const float* pos = (const float*)d_in[5];
    float* out = (float*)d_out;

    cudaFuncSetAttribute(mm_qkv,   cudaFuncAttributeMaxDynamicSharedMemorySize, SMEM_2);
    cudaFuncSetAttribute(mm_pos,   cudaFuncAttributeMaxDynamicSharedMemorySize, SMEM_1);
    cudaFuncSetAttribute(mm_score, cudaFuncAttributeMaxDynamicSharedMemorySize, SMEM_1);
    cudaFuncSetAttribute(mm_av,    cudaFuncAttributeMaxDynamicSharedMemorySize, SMEM_2);
    cudaFuncSetAttribute(mm_out,   cudaFuncAttributeMaxDynamicSharedMemorySize, SMEM_2);

    pack_x_kernel<<<4096, 256>>>(x);
    pack_w_kernel<<<1024, 256>>>(Wq, Wkv, Wo);
    pack_t_kernel<<<68, 256>>>(pos);

    mm_qkv  <<<dim3(24, 64),    128, SMEM_2>>>();
    mm_pos  <<<dim3(17, 512),   128, SMEM_1>>>();
    mm_score<<<dim3(16, 8, 64), 128, SMEM_1>>>();
    softmax_kernel<<<65536, 256>>>();
    mm_av   <<<dim3(8, 64),     128, SMEM_2>>>();
    mm_out  <<<dim3(8, 64),     128, SMEM_2>>>(bo, out);
}

// round 7
// speedup vs baseline: 2.6358x; 1.4310x over previous
#include <cuda_runtime.h>
#include <cuda_bf16.h>
#include <cuda_fp16.h>
#include <cstdint>

#define Nn    1024
#define NPp   1025
#define NPS   1028
#define BHb   64
#define MXm   8192

typedef __nv_bfloat16 bf16;

// ---------------- device scratch ----------------
__device__ bf16  g_xh [(size_t)MXm * 512],      g_xl [(size_t)MXm * 512];
__device__ bf16  g_wqh[(size_t)512 * 512],      g_wql[(size_t)512 * 512];
__device__ bf16  g_wkvh[(size_t)1024 * 512],    g_wkvl[(size_t)1024 * 512];
__device__ bf16  g_woh[(size_t)512 * 512],      g_wol[(size_t)512 * 512];
__device__ bf16  g_th [(size_t)1088 * 64],      g_tl [(size_t)1088 * 64];
__device__ bf16  g_qh [(size_t)BHb * Nn * 64],  g_ql [(size_t)BHb * Nn * 64];   // scaled by 0.125
__device__ bf16  g_kh [(size_t)BHb * Nn * 64],  g_kl [(size_t)BHb * Nn * 64];
__device__ bf16  g_vth[(size_t)BHb * 64 * Nn],  g_vtl[(size_t)BHb * 64 * Nn];   // [bh][d][j]
__device__ bf16  g_ch [(size_t)MXm * 512],      g_cl [(size_t)MXm * 512];
__device__ __half g_Ph[(size_t)BHb * Nn * NPS];                                  // pos dots (scaled)

// ---------------- smem geometry ----------------
#define STRB  144
#define A_HI  0u
#define A_LO  18432u
#define B_HI  36864u
#define B_LO  46080u
#define BUFB  55296u
#define SMEM_1 55296
#define SMEM_2 110592

// fused-attention smem layout
#define FQ_HI   0u
#define FQ_LO   18432u
#define FKV0    36864u
#define FKVSTR  36864u
#define FK_HI   0u
#define FK_LO   9216u
#define FV_HI   18432u
#define FV_LO   27648u
#define FREDM   110592u
#define FREDS   111616u
#define SMEM_FA 112640

#define LDS32(v, a) asm volatile("ld.shared.b32 %0, [%1];" : "=r"(v) : "r"(a))
#define CP16(d, s)  asm volatile("cp.async.ca.shared.global [%0], [%1], 16;" :: "r"(d), "l"(s))
#define CP_COMMIT() asm volatile("cp.async.commit_group;" ::: "memory")
#define CP_WAIT(n)  asm volatile("cp.async.wait_group %0;" :: "n"(n) : "memory")

static __device__ __forceinline__ uint32_t smem_u32(const void* p) {
    uint32_t a;
    asm("{ .reg .u64 t; cvta.to.shared.u64 t, %1; cvt.u32.u64 %0, t; }" : "=r"(a) : "l"(p));
    return a;
}
static __device__ __forceinline__ void split1(float v, bf16& h, bf16& l) {
    h = __float2bfloat16(v);
    l = __float2bfloat16(v - __bfloat162float(h));
}
static __device__ __forceinline__ void split2(float v0, float v1, uint32_t& h2, uint32_t& l2) {
    bf16 h0, l0, h1, l1;
    split1(v0, h0, l0); split1(v1, h1, l1);
    h2 = (uint32_t)__bfloat16_as_ushort(h0) | ((uint32_t)__bfloat16_as_ushort(h1) << 16);
    l2 = (uint32_t)__bfloat16_as_ushort(l0) | ((uint32_t)__bfloat16_as_ushort(l1) << 16);
}
static __device__ __forceinline__ void mma_bf16(float* d, const uint32_t* a, const uint32_t* b) {
    asm volatile("mma.sync.aligned.m16n8k16.row.col.f32.bf16.bf16.f32 "
                 "{%0,%1,%2,%3}, {%4,%5,%6,%7}, {%8,%9}, {%0,%1,%2,%3};"
                 : "+f"(d[0]), "+f"(d[1]), "+f"(d[2]), "+f"(d[3])
                 : "r"(a[0]), "r"(a[1]), "r"(a[2]), "r"(a[3]), "r"(b[0]), "r"(b[1]));
}

template <int R, int T>
static __device__ __forceinline__ void stage_cp(uint32_t sdst, const bf16* src, int lds, int t) {
    #pragma unroll
    for (int i = 0; i < R * 8 / T; i++) {
        int idx = t + i * T;
        int row = idx >> 3, ch = idx & 7;
        CP16(sdst + (uint32_t)row * STRB + (uint32_t)ch * 16,
             src + (size_t)row * lds + ch * 8);
    }
}

static __device__ __forceinline__ void stage_all(uint32_t sb,
                                                 const bf16* ah, const bf16* al, int ldsa,
                                                 const bf16* bh, const bf16* bl, int ldsb, int t) {
    stage_cp<128, 128>(sb + A_HI, ah, ldsa, t);
    stage_cp<128, 128>(sb + A_LO, al, ldsa, t);
    stage_cp<64, 128> (sb + B_HI, bh, ldsb, t);
    stage_cp<64, 128> (sb + B_LO, bl, ldsb, t);
    CP_COMMIT();
}

// term-major K=64 stage; warp tile 64x32 (plain GEMM kernels, 128 thr)
static __device__ __forceinline__ void compute_stage(uint32_t sb, int lane, int my, int nx,
                                                     float acc[4][4][4]) {
    const int r = lane >> 2, cc = lane & 3;
    #pragma unroll
    for (int ks = 0; ks < 4; ks++) {
        const uint32_t kb = (uint32_t)ks * 32 + (uint32_t)cc * 4;
        uint32_t ah[4][4], al[4][4], bh[4][2], bl[4][2];
        #pragma unroll
        for (int mi = 0; mi < 4; mi++) {
            uint32_t ad = sb + (uint32_t)(my * 64 + mi * 16 + r) * STRB + kb;
            LDS32(ah[mi][0], ad + A_HI);
            LDS32(ah[mi][1], ad + A_HI + 8 * STRB);
            LDS32(ah[mi][2], ad + A_HI + 16);
            LDS32(ah[mi][3], ad + A_HI + 8 * STRB + 16);
            LDS32(al[mi][0], ad + A_LO);
            LDS32(al[mi][1], ad + A_LO + 8 * STRB);
            LDS32(al[mi][2], ad + A_LO + 16);
            LDS32(al[mi][3], ad + A_LO + 8 * STRB + 16);
        }
        #pragma unroll
        for (int ni = 0; ni < 4; ni++) {
            uint32_t bd = sb + (uint32_t)(nx * 32 + ni * 8 + r) * STRB + kb;
            LDS32(bh[ni][0], bd + B_HI);
            LDS32(bh[ni][1], bd + B_HI + 16);
            LDS32(bl[ni][0], bd + B_LO);
            LDS32(bl[ni][1], bd + B_LO + 16);
        }
        #pragma unroll
        for (int ni = 0; ni < 4; ni++)
            #pragma unroll
            for (int mi = 0; mi < 4; mi++)
                mma_bf16(acc[mi][ni], ah[mi], bh[ni]);
        #pragma unroll
        for (int ni = 0; ni < 4; ni++)
            #pragma unroll
            for (int mi = 0; mi < 4; mi++)
                mma_bf16(acc[mi][ni], ah[mi], bl[ni]);
        #pragma unroll
        for (int ni = 0; ni < 4; ni++)
            #pragma unroll
            for (int mi = 0; mi < 4; mi++)
                mma_bf16(acc[mi][ni], al[mi], bh[ni]);
    }
}

// ===========================================================================
// Prep kernels
// ===========================================================================
__global__ void pack_x_kernel(const float* __restrict__ x) {
    size_t e = ((size_t)blockIdx.x * 256 + threadIdx.x) * 4;
    float4 v = *(const float4*)(x + e);
    uint32_t h0, l0, h1, l1;
    split2(v.x, v.y, h0, l0);
    split2(v.z, v.w, h1, l1);
    *(uint2*)&g_xh[e] = make_uint2(h0, h1);
    *(uint2*)&g_xl[e] = make_uint2(l0, l1);
}

__global__ void pack_w_kernel(const float* __restrict__ Wq, const float* __restrict__ Wkv,
                              const float* __restrict__ Wo) {
    size_t e0 = ((size_t)blockIdx.x * 256 + threadIdx.x) * 4;
    #pragma unroll
    for (int cc = 0; cc < 4; cc++) {
        size_t e = e0 + cc;
        bf16 h, l;
        if (e < 262144) {
            int k = (int)(e & 511), n = (int)(e >> 9);
            split1(Wq[(size_t)k * 512 + n], h, l);
            g_wqh[e] = h; g_wql[e] = l;
        } else if (e < 786432) {
            size_t m = e - 262144;
            int k = (int)(m & 511), n = (int)(m >> 9);
            split1(Wkv[(size_t)k * 1024 + n], h, l);
            g_wkvh[m] = h; g_wkvl[m] = l;
        } else {
            size_t m = e - 786432;
            int k = (int)(m & 511), n = (int)(m >> 9);
            split1(Wo[(size_t)k * 512 + n], h, l);
            g_woh[m] = h; g_wol[m] = l;
        }
    }
}

__global__ void pack_t_kernel(const float* __restrict__ T) {
    size_t e0 = ((size_t)blockIdx.x * 256 + threadIdx.x) * 4;
    #pragma unroll
    for (int cc = 0; cc < 4; cc++) {
        size_t e = e0 + cc;
        int p = (int)(e >> 6), d = (int)(e & 63);
        bf16 h = __float2bfloat16(0.f), l = h;
        if (p < NPp) split1(T[(size_t)p * 64 + d], h, l);
        g_th[e] = h; g_tl[e] = l;
    }
}

// ===========================================================================
// GEMM 1: QKV. grid(24, 64).  q scaled by 0.125 at write.
// ===========================================================================
__global__ __launch_bounds__(128) void mm_qkv() {
    extern __shared__ uint8_t smem[];
    const uint32_t sb = smem_u32(smem);
    const int t = threadIdx.x, lane = t & 31, wid = t >> 5;
    const int my = wid >> 1, nx = wid & 1;
    const int n0 = blockIdx.x * 64, m0 = blockIdx.y * 128;

    const bf16* ah = g_xh + (size_t)m0 * 512;
    const bf16* al = g_xl + (size_t)m0 * 512;
    const bf16* bh = (n0 < 512) ? (g_wqh + (size_t)n0 * 512) : (g_wkvh + (size_t)(n0 - 512) * 512);
    const bf16* bl = (n0 < 512) ? (g_wql + (size_t)n0 * 512) : (g_wkvl + (size_t)(n0 - 512) * 512);

    float acc[4][4][4] = {};
    stage_all(sb, ah, al, 512, bh, bl, 512, t);
    for (int s = 0; s < 8; s++) {
        if (s + 1 < 8) {
            stage_all(sb + ((s + 1) & 1) * BUFB, ah + (s + 1) * 64, al + (s + 1) * 64, 512,
                      bh + (s + 1) * 64, bl + (s + 1) * 64, 512, t);
            CP_WAIT(1);
        } else {
            CP_WAIT(0);
        }
        __syncthreads();
        compute_stage(sb + (s & 1) * BUFB, lane, my, nx, acc);
        __syncthreads();
    }

    const int b = m0 >> 10, i0 = m0 & 1023;
    const int region = n0 >> 9;
    const int h = (n0 >> 6) & 7;
    const int bh_idx = b * 8 + h;
    const int r = lane >> 2, cc = lane & 3;
    const float sc = (region == 0) ? 0.125f : 1.0f;

    if (region == 2) {
        #pragma unroll
        for (int mi = 0; mi < 4; mi++)
        #pragma unroll
        for (int ni = 0; ni < 4; ni++)
        #pragma unroll
        for (int g = 0; g < 2; g++) {
            int i = i0 + my * 64 + mi * 16 + r + g * 8;
            int d = nx * 32 + ni * 8 + cc * 2;
            bf16 h0, l0, h1, l1;
            split1(acc[mi][ni][2 * g],     h0, l0);
            split1(acc[mi][ni][2 * g + 1], h1, l1);
            g_vth[((size_t)bh_idx * 64 + d)     * 1024 + i] = h0;
            g_vtl[((size_t)bh_idx * 64 + d)     * 1024 + i] = l0;
            g_vth[((size_t)bh_idx * 64 + d + 1) * 1024 + i] = h1;
            g_vtl[((size_t)bh_idx * 64 + d + 1) * 1024 + i] = l1;
        }
    } else {
        bf16* dh = (region == 0 ? g_qh : g_kh) + ((size_t)bh_idx * 1024 + i0) * 64;
        bf16* dl = (region == 0 ? g_ql : g_kl) + ((size_t)bh_idx * 1024 + i0) * 64;
        #pragma unroll
        for (int mi = 0; mi < 4; mi++)
        #pragma unroll
        for (int ni = 0; ni < 4; ni++)
        #pragma unroll
        for (int g = 0; g < 2; g++) {
            int il = my * 64 + mi * 16 + r + g * 8;
            int d  = nx * 32 + ni * 8 + cc * 2;
            uint32_t h2, l2;
            split2(sc * acc[mi][ni][2 * g], sc * acc[mi][ni][2 * g + 1], h2, l2);
            *(uint32_t*)&dh[(size_t)il * 64 + d] = h2;
            *(uint32_t*)&dl[(size_t)il * 64 + d] = l2;
        }
    }
}

// ===========================================================================
// GEMM 2: P = q_scaled . T^T  -> fp16.  grid(17, 512)
// ===========================================================================
__global__ __launch_bounds__(128) void mm_pos() {
    extern __shared__ uint8_t smem[];
    const uint32_t sb = smem_u32(smem);
    const int t = threadIdx.x, lane = t & 31, wid = t >> 5;
    const int my = wid >> 1, nx = wid & 1;
    const int p0 = blockIdx.x * 64, m0 = blockIdx.y * 128;

    float acc[4][4][4] = {};
    stage_all(sb, g_qh + (size_t)m0 * 64, g_ql + (size_t)m0 * 64, 64,
              g_th + (size_t)p0 * 64, g_tl + (size_t)p0 * 64, 64, t);
    CP_WAIT(0);
    __syncthreads();
    compute_stage(sb, lane, my, nx, acc);

    const int r = lane >> 2, cc = lane & 3;
    #pragma unroll
    for (int mi = 0; mi < 4; mi++)
    #pragma unroll
    for (int ni = 0; ni < 4; ni++)
    #pragma unroll
    for (int g = 0; g < 2; g++) {
        int m = m0 + my * 64 + mi * 16 + r + g * 8;
        int p = p0 + nx * 32 + ni * 8 + cc * 2;
        if (p + 1 < NPp) {
            __half2 hv = __floats2half2_rn(acc[mi][ni][2 * g], acc[mi][ni][2 * g + 1]);
            *(__half2*)&g_Ph[(size_t)m * NPS + p] = hv;
        } else if (p < NPp) {
            g_Ph[(size_t)m * NPS + p] = __float2half(acc[mi][ni][2 * g]);
        }
    }
}

// ===========================================================================
// Fused attention: grid(8, 64), 256 thr.  Warps split j (wx) — O partials
// are reduced across wx through smem at the end.
// ===========================================================================
static __device__ __forceinline__ void fa_stage_kv(uint32_t kvb,
                                                   const bf16* kh, const bf16* kl,
                                                   const bf16* vh, const bf16* vl,
                                                   int j0, int t) {
    stage_cp<64, 256>(kvb + FK_HI, kh + (size_t)j0 * 64, 64, t);
    stage_cp<64, 256>(kvb + FK_LO, kl + (size_t)j0 * 64, 64, t);
    stage_cp<64, 256>(kvb + FV_HI, vh + j0, 1024, t);
    stage_cp<64, 256>(kvb + FV_LO, vl + j0, 1024, t);
    CP_COMMIT();
}

__global__ __launch_bounds__(256) void fa_kernel() {
    extern __shared__ uint8_t smem[];
    const uint32_t sb = smem_u32(smem);
    const int t = threadIdx.x, lane = t & 31, wid = t >> 5;
    const int wy = wid >> 1, wx = wid & 1;
    const int r = lane >> 2, cc = lane & 3;
    const int i0 = blockIdx.x * 128, bh = blockIdx.y;

    const bf16* qh = g_qh + ((size_t)bh * 1024 + i0) * 64;
    const bf16* ql = g_ql + ((size_t)bh * 1024 + i0) * 64;
    const bf16* kh = g_kh + (size_t)bh * 1024 * 64;
    const bf16* kl = g_kl + (size_t)bh * 1024 * 64;
    const bf16* vh = g_vth + (size_t)bh * 64 * 1024;
    const bf16* vl = g_vtl + (size_t)bh * 64 * 1024;
    const __half* Pb = g_Ph + (size_t)bh * 1024 * NPS;

    stage_cp<128, 256>(sb + FQ_HI, qh, 64, t);
    stage_cp<128, 256>(sb + FQ_LO, ql, 64, t);
    fa_stage_kv(sb + FKV0, kh, kl, vh, vl, 0, t);

    float m_run[2][2], l_run[2][2], oacc[2][8][4];
    #pragma unroll
    for (int mi = 0; mi < 2; mi++)
        #pragma unroll
        for (int g = 0; g < 2; g++) { m_run[mi][g] = -1e30f; l_run[mi][g] = 0.f; }
    #pragma unroll
    for (int mi = 0; mi < 2; mi++)
        #pragma unroll
        for (int dn = 0; dn < 8; dn++)
            #pragma unroll
            for (int e = 0; e < 4; e++) oacc[mi][dn][e] = 0.f;

    float* redm = (float*)(smem + FREDM);
    float* reds = (float*)(smem + FREDS);

    for (int jt = 0; jt < 16; jt++) {
        const uint32_t kvb = sb + FKV0 + (uint32_t)(jt & 1) * FKVSTR;
        CP_WAIT(0);
        __syncthreads();
        if (jt + 1 < 16)
            fa_stage_kv(sb + FKV0 + (uint32_t)((jt + 1) & 1) * FKVSTR,
                        kh, kl, vh, vl, (jt + 1) * 64, t);

        // ---- QK^T: warp rows wy*32..+31, cols wx*32..+31 ----
        float sacc[2][4][4];
        #pragma unroll
        for (int mi = 0; mi < 2; mi++)
            #pragma unroll
            for (int ni = 0; ni < 4; ni++)
                #pragma unroll
                for (int e = 0; e < 4; e++) sacc[mi][ni][e] = 0.f;

        #pragma unroll
        for (int ks = 0; ks < 4; ks++) {
            const uint32_t kb = (uint32_t)ks * 32 + (uint32_t)cc * 4;
            uint32_t qah[2][4], qal[2][4], kbh[4][2], kbl[4][2];
            #pragma unroll
            for (int mi = 0; mi < 2; mi++) {
                uint32_t ad = sb + (uint32_t)(wy * 32 + mi * 16 + r) * STRB + kb;
                LDS32(qah[mi][0], ad + FQ_HI);
                LDS32(qah[mi][1], ad + FQ_HI + 8 * STRB);
                LDS32(qah[mi][2], ad + FQ_HI + 16);
                LDS32(qah[mi][3], ad + FQ_HI + 8 * STRB + 16);
                LDS32(qal[mi][0], ad + FQ_LO);
                LDS32(qal[mi][1], ad + FQ_LO + 8 * STRB);
                LDS32(qal[mi][2], ad + FQ_LO + 16);
                LDS32(qal[mi][3], ad + FQ_LO + 8 * STRB + 16);
            }
            #pragma unroll
            for (int ni = 0; ni < 4; ni++) {
                uint32_t bd = kvb + (uint32_t)(wx * 32 + ni * 8 + r) * STRB + kb;
                LDS32(kbh[ni][0], bd + FK_HI);
                LDS32(kbh[ni][1], bd + FK_HI + 16);
                LDS32(kbl[ni][0], bd + FK_LO);
                LDS32(kbl[ni][1], bd + FK_LO + 16);
            }
            #pragma unroll
            for (int ni = 0; ni < 4; ni++)
                #pragma unroll
                for (int mi = 0; mi < 2; mi++)
                    mma_bf16(sacc[mi][ni], qah[mi], kbh[ni]);
            #pragma unroll
            for (int ni = 0; ni < 4; ni++)
                #pragma unroll
                for (int mi = 0; mi < 2; mi++)
                    mma_bf16(sacc[mi][ni], qah[mi], kbl[ni]);
            #pragma unroll
            for (int ni = 0; ni < 4; ni++)
                #pragma unroll
                for (int mi = 0; mi < 2; mi++)
                    mma_bf16(sacc[mi][ni], qal[mi], kbh[ni]);
        }

        // ---- positional term ----
        const int j0 = jt * 64;
        #pragma unroll
        for (int mi = 0; mi < 2; mi++)
            #pragma unroll
            for (int ni = 0; ni < 4; ni++)
                #pragma unroll
                for (int e = 0; e < 4; e++) {
                    int i = i0 + wy * 32 + mi * 16 + (e >> 1) * 8 + r;
                    int j = j0 + wx * 32 + ni * 8 + cc * 2 + (e & 1);
                    int dd = i - j;
                    dd = max(-512, min(512, dd));
                    sacc[mi][ni][e] += __half2float(Pb[(size_t)i * NPS + dd + 512]);
                }

        // ---- row max ----
        float mrow[2][2];
        #pragma unroll
        for (int mi = 0; mi < 2; mi++)
            #pragma unroll
            for (int g = 0; g < 2; g++) {
                float m = fmaxf(sacc[mi][0][2 * g], sacc[mi][0][2 * g + 1]);
                #pragma unroll
                for (int ni = 1; ni < 4; ni++)
                    m = fmaxf(m, fmaxf(sacc[mi][ni][2 * g], sacc[mi][ni][2 * g + 1]));
                m = fmaxf(m, __shfl_xor_sync(0xffffffffu, m, 1));
                m = fmaxf(m, __shfl_xor_sync(0xffffffffu, m, 2));
                mrow[mi][g] = m;
            }
        if (cc == 0) {
            #pragma unroll
            for (int mi = 0; mi < 2; mi++)
                #pragma unroll
                for (int g = 0; g < 2; g++)
                    redm[(wy * 32 + mi * 16 + g * 8 + r) * 2 + wx] = mrow[mi][g];
        }
        __syncthreads();

        float mnew[2][2], f[2][2];
        #pragma unroll
        for (int mi = 0; mi < 2; mi++)
            #pragma unroll
            for (int g = 0; g < 2; g++) {
                int lr = wy * 32 + mi * 16 + g * 8 + r;
                float tm = fmaxf(redm[lr * 2], redm[lr * 2 + 1]);
                float mn = fmaxf(m_run[mi][g], tm);
                f[mi][g] = __expf(m_run[mi][g] - mn);
                m_run[mi][g] = mn;
                mnew[mi][g] = mn;
            }

        // ---- exp + row sum ----
        #pragma unroll
        for (int mi = 0; mi < 2; mi++)
            #pragma unroll
            for (int ni = 0; ni < 4; ni++)
                #pragma unroll
                for (int e = 0; e < 4; e++)
                    sacc[mi][ni][e] = __expf(sacc[mi][ni][e] - mnew[mi][e >> 1]);

        float srow[2][2];
        #pragma unroll
        for (int mi = 0; mi < 2; mi++)
            #pragma unroll
            for (int g = 0; g < 2; g++) {
                float s = 0.f;
                #pragma unroll
                for (int ni = 0; ni < 4; ni++)
                    s += sacc[mi][ni][2 * g] + sacc[mi][ni][2 * g + 1];
                s += __shfl_xor_sync(0xffffffffu, s, 1);
                s += __shfl_xor_sync(0xffffffffu, s, 2);
                srow[mi][g] = s;
            }
        if (cc == 0) {
            #pragma unroll
            for (int mi = 0; mi < 2; mi++)
                #pragma unroll
                for (int g = 0; g < 2; g++)
                    reds[(wy * 32 + mi * 16 + g * 8 + r) * 2 + wx] = srow[mi][g];
        }
        __syncthreads();
        #pragma unroll
        for (int mi = 0; mi < 2; mi++)
            #pragma unroll
            for (int g = 0; g < 2; g++) {
                int lr = wy * 32 + mi * 16 + g * 8 + r;
                l_run[mi][g] = l_run[mi][g] * f[mi][g] + reds[lr * 2] + reds[lr * 2 + 1];
            }

        // ---- rescale O ----
        #pragma unroll
        for (int mi = 0; mi < 2; mi++)
            #pragma unroll
            for (int dn = 0; dn < 8; dn++)
                #pragma unroll
                for (int e = 0; e < 4; e++)
                    oacc[mi][dn][e] *= f[mi][e >> 1];

        // ---- SV (C->A identity; B from V^T) ----
        #pragma unroll
        for (int ks2 = 0; ks2 < 2; ks2++) {
            uint32_t vbh[8][2], vbl[8][2];
            #pragma unroll
            for (int dn = 0; dn < 8; dn++) {
                uint32_t vd = kvb + (uint32_t)(dn * 8 + r) * STRB
                            + (uint32_t)(wx * 64 + ks2 * 32 + cc * 4);
                LDS32(vbh[dn][0], vd + FV_HI);
                LDS32(vbh[dn][1], vd + FV_HI + 16);
                LDS32(vbl[dn][0], vd + FV_LO);
                LDS32(vbl[dn][1], vd + FV_LO + 16);
            }
            uint32_t pah[2][4], pal[2][4];
            #pragma unroll
            for (int mi = 0; mi < 2; mi++) {
                split2(sacc[mi][2 * ks2][0],     sacc[mi][2 * ks2][1],     pah[mi][0], pal[mi][0]);
                split2(sacc[mi][2 * ks2][2],     sacc[mi][2 * ks2][3],     pah[mi][1], pal[mi][1]);
                split2(sacc[mi][2 * ks2 + 1][0], sacc[mi][2 * ks2 + 1][1], pah[mi][2], pal[mi][2]);
                split2(sacc[mi][2 * ks2 + 1][2], sacc[mi][2 * ks2 + 1][3], pah[mi][3], pal[mi][3]);
            }
            #pragma unroll
            for (int mi = 0; mi < 2; mi++)
                #pragma unroll
                for (int dn = 0; dn < 8; dn++)
                    mma_bf16(oacc[mi][dn], pah[mi], vbh[dn]);
            #pragma unroll
            for (int mi = 0; mi < 2; mi++)
                #pragma unroll
                for (int dn = 0; dn < 8; dn++)
                    mma_bf16(oacc[mi][dn], pah[mi], vbl[dn]);
            #pragma unroll
            for (int mi = 0; mi < 2; mi++)
                #pragma unroll
                for (int dn = 0; dn < 8; dn++)
                    mma_bf16(oacc[mi][dn], pal[mi], vbh[dn]);
        }
    }

    // ---- cross-wx reduction of O partials via smem ----
    __syncthreads();                       // KV buffers now dead; reuse
    float* ored = (float*)(smem + FKV0);   // [wy][row 0..31][d 0..63]
    if (wx == 1) {
        #pragma unroll
        for (int mi = 0; mi < 2; mi++)
        #pragma unroll
        for (int dn = 0; dn < 8; dn++)
        #pragma unroll
        for (int g = 0; g < 2; g++) {
            int lr = mi * 16 + g * 8 + r;
            int d  = dn * 8 + cc * 2;
            *(float2*)&ored[(size_t)wy * 2048 + lr * 64 + d] =
                make_float2(oacc[mi][dn][2 * g], oacc[mi][dn][2 * g + 1]);
        }
    }
    __syncthreads();

    if (wx == 0) {
        const int b = bh >> 3, hh = bh & 7;
        float inv[2][2];
        #pragma unroll
        for (int mi = 0; mi < 2; mi++)
            #pragma unroll
            for (int g = 0; g < 2; g++) inv[mi][g] = 1.0f / l_run[mi][g];

        #pragma unroll
        for (int mi = 0; mi < 2; mi++)
        #pragma unroll
        for (int dn = 0; dn < 8; dn++)
        #pragma unroll
        for (int g = 0; g < 2; g++) {
            int lr = mi * 16 + g * 8 + r;
            int d  = dn * 8 + cc * 2;
            float2 other = *(float2*)&ored[(size_t)wy * 2048 + lr * 64 + d];
            float v0 = (oacc[mi][dn][2 * g]     + other.x) * inv[mi][g];
            float v1 = (oacc[mi][dn][2 * g + 1] + other.y) * inv[mi][g];
            int gi = i0 + wy * 32 + lr;
            uint32_t h2, l2;
            split2(v0, v1, h2, l2);
            size_t off = ((size_t)(b * 1024 + gi)) * 512 + hh * 64 + d;
            *(uint32_t*)&g_ch[off] = h2;
            *(uint32_t*)&g_cl[off] = l2;
        }
    }
}

// ===========================================================================
// GEMM 5: out = ctx @ Wo + bo.  grid(8, 64)
// ===========================================================================
__global__ __launch_bounds__(128) void mm_out(const float* __restrict__ bo,
                                              float* __restrict__ out) {
    extern __shared__ uint8_t smem[];
    const uint32_t sb = smem_u32(smem);
    const int t = threadIdx.x, lane = t & 31, wid = t >> 5;
    const int my = wid >> 1, nx = wid & 1;
    const int n0 = blockIdx.x * 64, m0 = blockIdx.y * 128;

    const bf16* ah = g_ch + (size_t)m0 * 512;
    const bf16* al = g_cl + (size_t)m0 * 512;
    const bf16* bhp = g_woh + (size_t)n0 * 512;
    const bf16* blp = g_wol + (size_t)n0 * 512;

    float acc[4][4][4] = {};
    stage_all(sb, ah, al, 512, bhp, blp, 512, t);
    for (int s = 0; s < 8; s++) {
        if (s + 1 < 8) {
            stage_all(sb + ((s + 1) & 1) * BUFB, ah + (s + 1) * 64, al + (s + 1) * 64, 512,
                      bhp + (s + 1) * 64, blp + (s + 1) * 64, 512, t);
            CP_WAIT(1);
        } else {
            CP_WAIT(0);
        }
        __syncthreads();
        compute_stage(sb + (s & 1) * BUFB, lane, my, nx, acc);
        __syncthreads();
    }

    const int r = lane >> 2, cc = lane & 3;
    #pragma unroll
    for (int mi = 0; mi < 4; mi++)
    #pragma unroll
    for (int ni = 0; ni < 4; ni++)
    #pragma unroll
    for (int g = 0; g < 2; g++) {
        int m = m0 + my * 64 + mi * 16 + r + g * 8;
        int n = n0 + nx * 32 + ni * 8 + cc * 2;
        float2 v;
        v.x = acc[mi][ni][2 * g]     + bo[n];
        v.y = acc[mi][ni][2 * g + 1] + bo[n + 1];
        *(float2*)&out[(size_t)m * 512 + n] = v;
    }
}

// ===========================================================================
extern "C" void kernel_launch(void* const* d_in, const int* in_sizes, int n_in,
                              void* d_out, int out_size) {
    const float* x   = (const float*)d_in[0];
    const float* Wq  = (const float*)d_in[1];
    const float* Wkv = (const float*)d_in[2];
    const float* Wo  = (const float*)d_in[3];
    const float* bo  = (const float*)d_in[4];
    const float* pos = (const float*)d_in[5];
    float* out = (float*)d_out;

    cudaFuncSetAttribute(mm_qkv,    cudaFuncAttributeMaxDynamicSharedMemorySize, SMEM_2);
    cudaFuncSetAttribute(mm_pos,    cudaFuncAttributeMaxDynamicSharedMemorySize, SMEM_1);
    cudaFuncSetAttribute(fa_kernel, cudaFuncAttributeMaxDynamicSharedMemorySize, SMEM_FA);
    cudaFuncSetAttribute(mm_out,    cudaFuncAttributeMaxDynamicSharedMemorySize, SMEM_2);

    pack_x_kernel<<<4096, 256>>>(x);
    pack_w_kernel<<<1024, 256>>>(Wq, Wkv, Wo);
    pack_t_kernel<<<68, 256>>>(pos);

    mm_qkv   <<<dim3(24, 64),  128, SMEM_2>>>();
    mm_pos   <<<dim3(17, 512), 128, SMEM_1>>>();
    fa_kernel<<<dim3(8, 64),   256, SMEM_FA>>>();
    mm_out   <<<dim3(8, 64),   128, SMEM_2>>>(bo, out);
}

// round 8
// speedup vs baseline: 2.6932x; 1.0218x over previous
#include <cuda_runtime.h>
#include <cuda_bf16.h>
#include <cuda_fp16.h>
#include <cstdint>

#define Nn    1024
#define NPp   1025
#define NPS   1028
#define BHb   64
#define MXm   8192

typedef __nv_bfloat16 bf16;

// ---------------- device scratch ----------------
__device__ bf16  g_xh [(size_t)MXm * 512],      g_xl [(size_t)MXm * 512];
__device__ bf16  g_wqh[(size_t)512 * 512],      g_wql[(size_t)512 * 512];
__device__ bf16  g_wkvh[(size_t)1024 * 512],    g_wkvl[(size_t)1024 * 512];
__device__ bf16  g_woh[(size_t)512 * 512],      g_wol[(size_t)512 * 512];
__device__ bf16  g_th [(size_t)1088 * 64],      g_tl [(size_t)1088 * 64];
__device__ bf16  g_qh [(size_t)BHb * Nn * 64],  g_ql [(size_t)BHb * Nn * 64];   // scaled by 0.125
__device__ bf16  g_kh [(size_t)BHb * Nn * 64],  g_kl [(size_t)BHb * Nn * 64];
__device__ bf16  g_vth[(size_t)BHb * 64 * Nn],  g_vtl[(size_t)BHb * 64 * Nn];   // [bh][d][j]
__device__ bf16  g_ch [(size_t)MXm * 512],      g_cl [(size_t)MXm * 512];
__device__ __half g_Ph[(size_t)BHb * Nn * NPS];                                  // pos dots (scaled)

// ---------------- smem geometry ----------------
#define STRB  144
#define A_HI  0u
#define A_LO  18432u
#define B_HI  36864u
#define B_LO  46080u
#define BUFB  55296u
#define SMEM_1 55296
#define SMEM_2 110592

// fused-attention smem layout
#define FQ_HI   0u
#define FQ_LO   18432u
#define FKV0    36864u
#define FKVSTR  36864u
#define FK_HI   0u
#define FK_LO   9216u
#define FV_HI   18432u
#define FV_LO   27648u
#define FREDM   110592u
#define FREDS   111616u
#define SMEM_FA 112640

#define CP16(d, s)  asm volatile("cp.async.ca.shared.global [%0], [%1], 16;" :: "r"(d), "l"(s))
#define CP_COMMIT() asm volatile("cp.async.commit_group;" ::: "memory")
#define CP_WAIT(n)  asm volatile("cp.async.wait_group %0;" :: "n"(n) : "memory")

// warp-collective 4-matrix fragment load (8x8 b16 atoms)
#define LDMX4(r0, r1, r2, r3, a) \
    asm volatile("ldmatrix.sync.aligned.m8n8.x4.shared.b16 {%0,%1,%2,%3}, [%4];" \
                 : "=r"(r0), "=r"(r1), "=r"(r2), "=r"(r3) : "r"(a))

static __device__ __forceinline__ uint32_t smem_u32(const void* p) {
    uint32_t a;
    asm("{ .reg .u64 t; cvta.to.shared.u64 t, %1; cvt.u32.u64 %0, t; }" : "=r"(a) : "l"(p));
    return a;
}
static __device__ __forceinline__ void split1(float v, bf16& h, bf16& l) {
    h = __float2bfloat16(v);
    l = __float2bfloat16(v - __bfloat162float(h));
}
static __device__ __forceinline__ void split2(float v0, float v1, uint32_t& h2, uint32_t& l2) {
    bf16 h0, l0, h1, l1;
    split1(v0, h0, l0); split1(v1, h1, l1);
    h2 = (uint32_t)__bfloat16_as_ushort(h0) | ((uint32_t)__bfloat16_as_ushort(h1) << 16);
    l2 = (uint32_t)__bfloat16_as_ushort(l0) | ((uint32_t)__bfloat16_as_ushort(l1) << 16);
}
static __device__ __forceinline__ void mma_bf16(float* d, const uint32_t* a, const uint32_t* b) {
    asm volatile("mma.sync.aligned.m16n8k16.row.col.f32.bf16.bf16.f32 "
                 "{%0,%1,%2,%3}, {%4,%5,%6,%7}, {%8,%9}, {%0,%1,%2,%3};"
                 : "+f"(d[0]), "+f"(d[1]), "+f"(d[2]), "+f"(d[3])
                 : "r"(a[0]), "r"(a[1]), "r"(a[2]), "r"(a[3]), "r"(b[0]), "r"(b[1]));
}

template <int R, int T>
static __device__ __forceinline__ void stage_cp(uint32_t sdst, const bf16* src, int lds, int t) {
    #pragma unroll
    for (int i = 0; i < R * 8 / T; i++) {
        int idx = t + i * T;
        int row = idx >> 3, ch = idx & 7;
        CP16(sdst + (uint32_t)row * STRB + (uint32_t)ch * 16,
             src + (size_t)row * lds + ch * 8);
    }
}

static __device__ __forceinline__ void stage_all(uint32_t sb,
                                                 const bf16* ah, const bf16* al, int ldsa,
                                                 const bf16* bh, const bf16* bl, int ldsb, int t) {
    stage_cp<128, 128>(sb + A_HI, ah, ldsa, t);
    stage_cp<128, 128>(sb + A_LO, al, ldsa, t);
    stage_cp<64, 128> (sb + B_HI, bh, ldsb, t);
    stage_cp<64, 128> (sb + B_LO, bl, ldsb, t);
    CP_COMMIT();
}

// lane-offset helpers for ldmatrix addressing
// A (m-major rows, k contiguous): row = lane&15, +16B if lane>=16
static __device__ __forceinline__ uint32_t lda_off(int lane) {
    return (uint32_t)(lane & 15) * STRB + (uint32_t)(lane & 16);
}
// B (n-major rows, k contiguous), x4 covers two 8-row n-blocks:
// n_off = (lane&7) + (lane&16)/2, koff = (lane&8)*2
static __device__ __forceinline__ uint32_t ldb_off(int lane) {
    return (uint32_t)((lane & 7) + ((lane & 16) >> 1)) * STRB + (uint32_t)((lane & 8) << 1);
}

// term-major K=64 stage; warp tile 64x32 (plain GEMM kernels, 128 thr)
static __device__ __forceinline__ void compute_stage(uint32_t sb, int lane, int my, int nx,
                                                     float acc[4][4][4]) {
    const uint32_t a_base = sb + (uint32_t)(my * 64) * STRB + lda_off(lane);
    const uint32_t b_base = sb + (uint32_t)(nx * 32) * STRB + ldb_off(lane);
    #pragma unroll
    for (int ks = 0; ks < 4; ks++) {
        uint32_t ah[4][4], al[4][4], bh[4][2], bl[4][2];
        #pragma unroll
        for (int mi = 0; mi < 4; mi++) {
            uint32_t ad = a_base + (uint32_t)(mi * 16) * STRB + (uint32_t)(ks * 32);
            LDMX4(ah[mi][0], ah[mi][1], ah[mi][2], ah[mi][3], ad + A_HI);
            LDMX4(al[mi][0], al[mi][1], al[mi][2], al[mi][3], ad + A_LO);
        }
        #pragma unroll
        for (int p = 0; p < 2; p++) {
            uint32_t bd = b_base + (uint32_t)(p * 16) * STRB + (uint32_t)(ks * 32);
            LDMX4(bh[2 * p][0], bh[2 * p][1], bh[2 * p + 1][0], bh[2 * p + 1][1], bd + B_HI);
            LDMX4(bl[2 * p][0], bl[2 * p][1], bl[2 * p + 1][0], bl[2 * p + 1][1], bd + B_LO);
        }
        #pragma unroll
        for (int ni = 0; ni < 4; ni++)
            #pragma unroll
            for (int mi = 0; mi < 4; mi++)
                mma_bf16(acc[mi][ni], ah[mi], bh[ni]);
        #pragma unroll
        for (int ni = 0; ni < 4; ni++)
            #pragma unroll
            for (int mi = 0; mi < 4; mi++)
                mma_bf16(acc[mi][ni], ah[mi], bl[ni]);
        #pragma unroll
        for (int ni = 0; ni < 4; ni++)
            #pragma unroll
            for (int mi = 0; mi < 4; mi++)
                mma_bf16(acc[mi][ni], al[mi], bh[ni]);
    }
}

// ===========================================================================
// Prep kernels
// ===========================================================================
__global__ void pack_x_kernel(const float* __restrict__ x) {
    size_t e = ((size_t)blockIdx.x * 256 + threadIdx.x) * 4;
    float4 v = *(const float4*)(x + e);
    uint32_t h0, l0, h1, l1;
    split2(v.x, v.y, h0, l0);
    split2(v.z, v.w, h1, l1);
    *(uint2*)&g_xh[e] = make_uint2(h0, h1);
    *(uint2*)&g_xl[e] = make_uint2(l0, l1);
}

__global__ void pack_w_kernel(const float* __restrict__ Wq, const float* __restrict__ Wkv,
                              const float* __restrict__ Wo) {
    size_t e0 = ((size_t)blockIdx.x * 256 + threadIdx.x) * 4;
    #pragma unroll
    for (int cc = 0; cc < 4; cc++) {
        size_t e = e0 + cc;
        bf16 h, l;
        if (e < 262144) {
            int k = (int)(e & 511), n = (int)(e >> 9);
            split1(Wq[(size_t)k * 512 + n], h, l);
            g_wqh[e] = h; g_wql[e] = l;
        } else if (e < 786432) {
            size_t m = e - 262144;
            int k = (int)(m & 511), n = (int)(m >> 9);
            split1(Wkv[(size_t)k * 1024 + n], h, l);
            g_wkvh[m] = h; g_wkvl[m] = l;
        } else {
            size_t m = e - 786432;
            int k = (int)(m & 511), n = (int)(m >> 9);
            split1(Wo[(size_t)k * 512 + n], h, l);
            g_woh[m] = h; g_wol[m] = l;
        }
    }
}

__global__ void pack_t_kernel(const float* __restrict__ T) {
    size_t e0 = ((size_t)blockIdx.x * 256 + threadIdx.x) * 4;
    #pragma unroll
    for (int cc = 0; cc < 4; cc++) {
        size_t e = e0 + cc;
        int p = (int)(e >> 6), d = (int)(e & 63);
        bf16 h = __float2bfloat16(0.f), l = h;
        if (p < NPp) split1(T[(size_t)p * 64 + d], h, l);
        g_th[e] = h; g_tl[e] = l;
    }
}

// ===========================================================================
// GEMM 1: QKV. grid(24, 64).  q scaled by 0.125 at write.
// ===========================================================================
__global__ __launch_bounds__(128) void mm_qkv() {
    extern __shared__ uint8_t smem[];
    const uint32_t sb = smem_u32(smem);
    const int t = threadIdx.x, lane = t & 31, wid = t >> 5;
    const int my = wid >> 1, nx = wid & 1;
    const int n0 = blockIdx.x * 64, m0 = blockIdx.y * 128;

    const bf16* ah = g_xh + (size_t)m0 * 512;
    const bf16* al = g_xl + (size_t)m0 * 512;
    const bf16* bh = (n0 < 512) ? (g_wqh + (size_t)n0 * 512) : (g_wkvh + (size_t)(n0 - 512) * 512);
    const bf16* bl = (n0 < 512) ? (g_wql + (size_t)n0 * 512) : (g_wkvl + (size_t)(n0 - 512) * 512);

    float acc[4][4][4] = {};
    stage_all(sb, ah, al, 512, bh, bl, 512, t);
    for (int s = 0; s < 8; s++) {
        if (s + 1 < 8) {
            stage_all(sb + ((s + 1) & 1) * BUFB, ah + (s + 1) * 64, al + (s + 1) * 64, 512,
                      bh + (s + 1) * 64, bl + (s + 1) * 64, 512, t);
            CP_WAIT(1);
        } else {
            CP_WAIT(0);
        }
        __syncthreads();
        compute_stage(sb + (s & 1) * BUFB, lane, my, nx, acc);
        __syncthreads();
    }

    const int b = m0 >> 10, i0 = m0 & 1023;
    const int region = n0 >> 9;
    const int h = (n0 >> 6) & 7;
    const int bh_idx = b * 8 + h;
    const int r = lane >> 2, cc = lane & 3;
    const float sc = (region == 0) ? 0.125f : 1.0f;

    if (region == 2) {
        #pragma unroll
        for (int mi = 0; mi < 4; mi++)
        #pragma unroll
        for (int ni = 0; ni < 4; ni++)
        #pragma unroll
        for (int g = 0; g < 2; g++) {
            int i = i0 + my * 64 + mi * 16 + r + g * 8;
            int d = nx * 32 + ni * 8 + cc * 2;
            bf16 h0, l0, h1, l1;
            split1(acc[mi][ni][2 * g],     h0, l0);
            split1(acc[mi][ni][2 * g + 1], h1, l1);
            g_vth[((size_t)bh_idx * 64 + d)     * 1024 + i] = h0;
            g_vtl[((size_t)bh_idx * 64 + d)     * 1024 + i] = l0;
            g_vth[((size_t)bh_idx * 64 + d + 1) * 1024 + i] = h1;
            g_vtl[((size_t)bh_idx * 64 + d + 1) * 1024 + i] = l1;
        }
    } else {
        bf16* dh = (region == 0 ? g_qh : g_kh) + ((size_t)bh_idx * 1024 + i0) * 64;
        bf16* dl = (region == 0 ? g_ql : g_kl) + ((size_t)bh_idx * 1024 + i0) * 64;
        #pragma unroll
        for (int mi = 0; mi < 4; mi++)
        #pragma unroll
        for (int ni = 0; ni < 4; ni++)
        #pragma unroll
        for (int g = 0; g < 2; g++) {
            int il = my * 64 + mi * 16 + r + g * 8;
            int d  = nx * 32 + ni * 8 + cc * 2;
            uint32_t h2, l2;
            split2(sc * acc[mi][ni][2 * g], sc * acc[mi][ni][2 * g + 1], h2, l2);
            *(uint32_t*)&dh[(size_t)il * 64 + d] = h2;
            *(uint32_t*)&dl[(size_t)il * 64 + d] = l2;
        }
    }
}

// ===========================================================================
// GEMM 2: P = q_scaled . T^T  -> fp16.  grid(17, 512)
// ===========================================================================
__global__ __launch_bounds__(128) void mm_pos() {
    extern __shared__ uint8_t smem[];
    const uint32_t sb = smem_u32(smem);
    const int t = threadIdx.x, lane = t & 31, wid = t >> 5;
    const int my = wid >> 1, nx = wid & 1;
    const int p0 = blockIdx.x * 64, m0 = blockIdx.y * 128;

    float acc[4][4][4] = {};
    stage_all(sb, g_qh + (size_t)m0 * 64, g_ql + (size_t)m0 * 64, 64,
              g_th + (size_t)p0 * 64, g_tl + (size_t)p0 * 64, 64, t);
    CP_WAIT(0);
    __syncthreads();
    compute_stage(sb, lane, my, nx, acc);

    const int r = lane >> 2, cc = lane & 3;
    #pragma unroll
    for (int mi = 0; mi < 4; mi++)
    #pragma unroll
    for (int ni = 0; ni < 4; ni++)
    #pragma unroll
    for (int g = 0; g < 2; g++) {
        int m = m0 + my * 64 + mi * 16 + r + g * 8;
        int p = p0 + nx * 32 + ni * 8 + cc * 2;
        if (p + 1 < NPp) {
            __half2 hv = __floats2half2_rn(acc[mi][ni][2 * g], acc[mi][ni][2 * g + 1]);
            *(__half2*)&g_Ph[(size_t)m * NPS + p] = hv;
        } else if (p < NPp) {
            g_Ph[(size_t)m * NPS + p] = __float2half(acc[mi][ni][2 * g]);
        }
    }
}

// ===========================================================================
// Fused attention: grid(8, 64), 256 thr.  Warps split j (wx); O partials
// reduced across wx through smem at the end.
// ===========================================================================
static __device__ __forceinline__ void fa_stage_kv(uint32_t kvb,
                                                   const bf16* kh, const bf16* kl,
                                                   const bf16* vh, const bf16* vl,
                                                   int j0, int t) {
    stage_cp<64, 256>(kvb + FK_HI, kh + (size_t)j0 * 64, 64, t);
    stage_cp<64, 256>(kvb + FK_LO, kl + (size_t)j0 * 64, 64, t);
    stage_cp<64, 256>(kvb + FV_HI, vh + j0, 1024, t);
    stage_cp<64, 256>(kvb + FV_LO, vl + j0, 1024, t);
    CP_COMMIT();
}

__global__ __launch_bounds__(256) void fa_kernel() {
    extern __shared__ uint8_t smem[];
    const uint32_t sb = smem_u32(smem);
    const int t = threadIdx.x, lane = t & 31, wid = t >> 5;
    const int wy = wid >> 1, wx = wid & 1;
    const int r = lane >> 2, cc = lane & 3;
    const int i0 = blockIdx.x * 128, bh = blockIdx.y;

    const bf16* qh = g_qh + ((size_t)bh * 1024 + i0) * 64;
    const bf16* ql = g_ql + ((size_t)bh * 1024 + i0) * 64;
    const bf16* kh = g_kh + (size_t)bh * 1024 * 64;
    const bf16* kl = g_kl + (size_t)bh * 1024 * 64;
    const bf16* vh = g_vth + (size_t)bh * 64 * 1024;
    const bf16* vl = g_vtl + (size_t)bh * 64 * 1024;
    const __half* Pb = g_Ph + (size_t)bh * 1024 * NPS;

    stage_cp<128, 256>(sb + FQ_HI, qh, 64, t);
    stage_cp<128, 256>(sb + FQ_LO, ql, 64, t);
    fa_stage_kv(sb + FKV0, kh, kl, vh, vl, 0, t);

    const uint32_t q_base = sb + (uint32_t)(wy * 32) * STRB + lda_off(lane);
    const uint32_t k_rel  = (uint32_t)(wx * 32) * STRB + ldb_off(lane);
    const uint32_t v_rel  = ldb_off(lane) + (uint32_t)(wx * 64);

    float m_run[2][2], l_run[2][2], oacc[2][8][4];
    #pragma unroll
    for (int mi = 0; mi < 2; mi++)
        #pragma unroll
        for (int g = 0; g < 2; g++) { m_run[mi][g] = -1e30f; l_run[mi][g] = 0.f; }
    #pragma unroll
    for (int mi = 0; mi < 2; mi++)
        #pragma unroll
        for (int dn = 0; dn < 8; dn++)
            #pragma unroll
            for (int e = 0; e < 4; e++) oacc[mi][dn][e] = 0.f;

    float* redm = (float*)(smem + FREDM);
    float* reds = (float*)(smem + FREDS);

    for (int jt = 0; jt < 16; jt++) {
        const uint32_t kvb = sb + FKV0 + (uint32_t)(jt & 1) * FKVSTR;
        CP_WAIT(0);
        __syncthreads();
        if (jt + 1 < 16)
            fa_stage_kv(sb + FKV0 + (uint32_t)((jt + 1) & 1) * FKVSTR,
                        kh, kl, vh, vl, (jt + 1) * 64, t);

        // ---- QK^T: warp rows wy*32..+31, cols wx*32..+31 ----
        float sacc[2][4][4];
        #pragma unroll
        for (int mi = 0; mi < 2; mi++)
            #pragma unroll
            for (int ni = 0; ni < 4; ni++)
                #pragma unroll
                for (int e = 0; e < 4; e++) sacc[mi][ni][e] = 0.f;

        #pragma unroll
        for (int ks = 0; ks < 4; ks++) {
            uint32_t qah[2][4], qal[2][4], kbh[4][2], kbl[4][2];
            #pragma unroll
            for (int mi = 0; mi < 2; mi++) {
                uint32_t ad = q_base + (uint32_t)(mi * 16) * STRB + (uint32_t)(ks * 32);
                LDMX4(qah[mi][0], qah[mi][1], qah[mi][2], qah[mi][3], ad + FQ_HI);
                LDMX4(qal[mi][0], qal[mi][1], qal[mi][2], qal[mi][3], ad + FQ_LO);
            }
            #pragma unroll
            for (int p = 0; p < 2; p++) {
                uint32_t bd = kvb + k_rel + (uint32_t)(p * 16) * STRB + (uint32_t)(ks * 32);
                LDMX4(kbh[2 * p][0], kbh[2 * p][1], kbh[2 * p + 1][0], kbh[2 * p + 1][1], bd + FK_HI);
                LDMX4(kbl[2 * p][0], kbl[2 * p][1], kbl[2 * p + 1][0], kbl[2 * p + 1][1], bd + FK_LO);
            }
            #pragma unroll
            for (int ni = 0; ni < 4; ni++)
                #pragma unroll
                for (int mi = 0; mi < 2; mi++)
                    mma_bf16(sacc[mi][ni], qah[mi], kbh[ni]);
            #pragma unroll
            for (int ni = 0; ni < 4; ni++)
                #pragma unroll
                for (int mi = 0; mi < 2; mi++)
                    mma_bf16(sacc[mi][ni], qah[mi], kbl[ni]);
            #pragma unroll
            for (int ni = 0; ni < 4; ni++)
                #pragma unroll
                for (int mi = 0; mi < 2; mi++)
                    mma_bf16(sacc[mi][ni], qal[mi], kbh[ni]);
        }

        // ---- positional term ----
        const int j0 = jt * 64;
        #pragma unroll
        for (int mi = 0; mi < 2; mi++)
            #pragma unroll
            for (int ni = 0; ni < 4; ni++)
                #pragma unroll
                for (int e = 0; e < 4; e++) {
                    int i = i0 + wy * 32 + mi * 16 + (e >> 1) * 8 + r;
                    int j = j0 + wx * 32 + ni * 8 + cc * 2 + (e & 1);
                    int dd = i - j;
                    dd = max(-512, min(512, dd));
                    sacc[mi][ni][e] += __half2float(Pb[(size_t)i * NPS + dd + 512]);
                }

        // ---- row max ----
        float mrow[2][2];
        #pragma unroll
        for (int mi = 0; mi < 2; mi++)
            #pragma unroll
            for (int g = 0; g < 2; g++) {
                float m = fmaxf(sacc[mi][0][2 * g], sacc[mi][0][2 * g + 1]);
                #pragma unroll
                for (int ni = 1; ni < 4; ni++)
                    m = fmaxf(m, fmaxf(sacc[mi][ni][2 * g], sacc[mi][ni][2 * g + 1]));
                m = fmaxf(m, __shfl_xor_sync(0xffffffffu, m, 1));
                m = fmaxf(m, __shfl_xor_sync(0xffffffffu, m, 2));
                mrow[mi][g] = m;
            }
        if (cc == 0) {
            #pragma unroll
            for (int mi = 0; mi < 2; mi++)
                #pragma unroll
                for (int g = 0; g < 2; g++)
                    redm[(wy * 32 + mi * 16 + g * 8 + r) * 2 + wx] = mrow[mi][g];
        }
        __syncthreads();

        float mnew[2][2], f[2][2];
        #pragma unroll
        for (int mi = 0; mi < 2; mi++)
            #pragma unroll
            for (int g = 0; g < 2; g++) {
                int lr = wy * 32 + mi * 16 + g * 8 + r;
                float tm = fmaxf(redm[lr * 2], redm[lr * 2 + 1]);
                float mn = fmaxf(m_run[mi][g], tm);
                f[mi][g] = __expf(m_run[mi][g] - mn);
                m_run[mi][g] = mn;
                mnew[mi][g] = mn;
            }

        // ---- exp + row sum ----
        #pragma unroll
        for (int mi = 0; mi < 2; mi++)
            #pragma unroll
            for (int ni = 0; ni < 4; ni++)
                #pragma unroll
                for (int e = 0; e < 4; e++)
                    sacc[mi][ni][e] = __expf(sacc[mi][ni][e] - mnew[mi][e >> 1]);

        float srow[2][2];
        #pragma unroll
        for (int mi = 0; mi < 2; mi++)
            #pragma unroll
            for (int g = 0; g < 2; g++) {
                float s = 0.f;
                #pragma unroll
                for (int ni = 0; ni < 4; ni++)
                    s += sacc[mi][ni][2 * g] + sacc[mi][ni][2 * g + 1];
                s += __shfl_xor_sync(0xffffffffu, s, 1);
                s += __shfl_xor_sync(0xffffffffu, s, 2);
                srow[mi][g] = s;
            }
        if (cc == 0) {
            #pragma unroll
            for (int mi = 0; mi < 2; mi++)
                #pragma unroll
                for (int g = 0; g < 2; g++)
                    reds[(wy * 32 + mi * 16 + g * 8 + r) * 2 + wx] = srow[mi][g];
        }
        __syncthreads();
        #pragma unroll
        for (int mi = 0; mi < 2; mi++)
            #pragma unroll
            for (int g = 0; g < 2; g++) {
                int lr = wy * 32 + mi * 16 + g * 8 + r;
                l_run[mi][g] = l_run[mi][g] * f[mi][g] + reds[lr * 2] + reds[lr * 2 + 1];
            }

        // ---- rescale O ----
        #pragma unroll
        for (int mi = 0; mi < 2; mi++)
            #pragma unroll
            for (int dn = 0; dn < 8; dn++)
                #pragma unroll
                for (int e = 0; e < 4; e++)
                    oacc[mi][dn][e] *= f[mi][e >> 1];

        // ---- SV (C->A identity; B from V^T via ldmatrix) ----
        #pragma unroll
        for (int ks2 = 0; ks2 < 2; ks2++) {
            uint32_t vbh[8][2], vbl[8][2];
            #pragma unroll
            for (int p3 = 0; p3 < 4; p3++) {
                uint32_t vd = kvb + v_rel + (uint32_t)(p3 * 16) * STRB + (uint32_t)(ks2 * 32);
                LDMX4(vbh[2 * p3][0], vbh[2 * p3][1], vbh[2 * p3 + 1][0], vbh[2 * p3 + 1][1],
                      vd + FV_HI);
                LDMX4(vbl[2 * p3][0], vbl[2 * p3][1], vbl[2 * p3 + 1][0], vbl[2 * p3 + 1][1],
                      vd + FV_LO);
            }
            uint32_t pah[2][4], pal[2][4];
            #pragma unroll
            for (int mi = 0; mi < 2; mi++) {
                split2(sacc[mi][2 * ks2][0],     sacc[mi][2 * ks2][1],     pah[mi][0], pal[mi][0]);
                split2(sacc[mi][2 * ks2][2],     sacc[mi][2 * ks2][3],     pah[mi][1], pal[mi][1]);
                split2(sacc[mi][2 * ks2 + 1][0], sacc[mi][2 * ks2 + 1][1], pah[mi][2], pal[mi][2]);
                split2(sacc[mi][2 * ks2 + 1][2], sacc[mi][2 * ks2 + 1][3], pah[mi][3], pal[mi][3]);
            }
            #pragma unroll
            for (int mi = 0; mi < 2; mi++)
                #pragma unroll
                for (int dn = 0; dn < 8; dn++)
                    mma_bf16(oacc[mi][dn], pah[mi], vbh[dn]);
            #pragma unroll
            for (int mi = 0; mi < 2; mi++)
                #pragma unroll
                for (int dn = 0; dn < 8; dn++)
                    mma_bf16(oacc[mi][dn], pah[mi], vbl[dn]);
            #pragma unroll
            for (int mi = 0; mi < 2; mi++)
                #pragma unroll
                for (int dn = 0; dn < 8; dn++)
                    mma_bf16(oacc[mi][dn], pal[mi], vbh[dn]);
        }
    }

    // ---- cross-wx reduction of O partials via smem ----
    __syncthreads();                       // KV buffers now dead; reuse
    float* ored = (float*)(smem + FKV0);   // [wy][row 0..31][d 0..63]
    if (wx == 1) {
        #pragma unroll
        for (int mi = 0; mi < 2; mi++)
        #pragma unroll
        for (int dn = 0; dn < 8; dn++)
        #pragma unroll
        for (int g = 0; g < 2; g++) {
            int lr = mi * 16 + g * 8 + r;
            int d  = dn * 8 + cc * 2;
            *(float2*)&ored[(size_t)wy * 2048 + lr * 64 + d] =
                make_float2(oacc[mi][dn][2 * g], oacc[mi][dn][2 * g + 1]);
        }
    }
    __syncthreads();

    if (wx == 0) {
        const int b = bh >> 3, hh = bh & 7;
        float inv[2][2];
        #pragma unroll
        for (int mi = 0; mi < 2; mi++)
            #pragma unroll
            for (int g = 0; g < 2; g++) inv[mi][g] = 1.0f / l_run[mi][g];

        #pragma unroll
        for (int mi = 0; mi < 2; mi++)
        #pragma unroll
        for (int dn = 0; dn < 8; dn++)
        #pragma unroll
        for (int g = 0; g < 2; g++) {
            int lr = mi * 16 + g * 8 + r;
            int d  = dn * 8 + cc * 2;
            float2 other = *(float2*)&ored[(size_t)wy * 2048 + lr * 64 + d];
            float v0 = (oacc[mi][dn][2 * g]     + other.x) * inv[mi][g];
            float v1 = (oacc[mi][dn][2 * g + 1] + other.y) * inv[mi][g];
            int gi = i0 + wy * 32 + lr;
            uint32_t h2, l2;
            split2(v0, v1, h2, l2);
            size_t off = ((size_t)(b * 1024 + gi)) * 512 + hh * 64 + d;
            *(uint32_t*)&g_ch[off] = h2;
            *(uint32_t*)&g_cl[off] = l2;
        }
    }
}

// ===========================================================================
// GEMM 5: out = ctx @ Wo + bo.  grid(8, 64)
// ===========================================================================
__global__ __launch_bounds__(128) void mm_out(const float* __restrict__ bo,
                                              float* __restrict__ out) {
    extern __shared__ uint8_t smem[];
    const uint32_t sb = smem_u32(smem);
    const int t = threadIdx.x, lane = t & 31, wid = t >> 5;
    const int my = wid >> 1, nx = wid & 1;
    const int n0 = blockIdx.x * 64, m0 = blockIdx.y * 128;

    const bf16* ah = g_ch + (size_t)m0 * 512;
    const bf16* al = g_cl + (size_t)m0 * 512;
    const bf16* bhp = g_woh + (size_t)n0 * 512;
    const bf16* blp = g_wol + (size_t)n0 * 512;

    float acc[4][4][4] = {};
    stage_all(sb, ah, al, 512, bhp, blp, 512, t);
    for (int s = 0; s < 8; s++) {
        if (s + 1 < 8) {
            stage_all(sb + ((s + 1) & 1) * BUFB, ah + (s + 1) * 64, al + (s + 1) * 64, 512,
                      bhp + (s + 1) * 64, blp + (s + 1) * 64, 512, t);
            CP_WAIT(1);
        } else {
            CP_WAIT(0);
        }
        __syncthreads();
        compute_stage(sb + (s & 1) * BUFB, lane, my, nx, acc);
        __syncthreads();
    }

    const int r = lane >> 2, cc = lane & 3;
    #pragma unroll
    for (int mi = 0; mi < 4; mi++)
    #pragma unroll
    for (int ni = 0; ni < 4; ni++)
    #pragma unroll
    for (int g = 0; g < 2; g++) {
        int m = m0 + my * 64 + mi * 16 + r + g * 8;
        int n = n0 + nx * 32 + ni * 8 + cc * 2;
        float2 v;
        v.x = acc[mi][ni][2 * g]     + bo[n];
        v.y = acc[mi][ni][2 * g + 1] + bo[n + 1];
        *(float2*)&out[(size_t)m * 512 + n] = v;
    }
}

// ===========================================================================
extern "C" void kernel_launch(void* const* d_in, const int* in_sizes, int n_in,
                              void* d_out, int out_size) {
    const float* x   = (const float*)d_in[0];
    const float* Wq  = (const float*)d_in[1];
    const float* Wkv = (const float*)d_in[2];
    const float* Wo  = (const float*)d_in[3];
    const float* bo  = (const float*)d_in[4];
    const float* pos = (const float*)d_in[5];
    float* out = (float*)d_out;

    cudaFuncSetAttribute(mm_qkv,    cudaFuncAttributeMaxDynamicSharedMemorySize, SMEM_2);
    cudaFuncSetAttribute(mm_pos,    cudaFuncAttributeMaxDynamicSharedMemorySize, SMEM_1);
    cudaFuncSetAttribute(fa_kernel, cudaFuncAttributeMaxDynamicSharedMemorySize, SMEM_FA);
    cudaFuncSetAttribute(mm_out,    cudaFuncAttributeMaxDynamicSharedMemorySize, SMEM_2);

    pack_x_kernel<<<4096, 256>>>(x);
    pack_w_kernel<<<1024, 256>>>(Wq, Wkv, Wo);
    pack_t_kernel<<<68, 256>>>(pos);

    mm_qkv   <<<dim3(24, 64),  128, SMEM_2>>>();
    mm_pos   <<<dim3(17, 512), 128, SMEM_1>>>();
    fa_kernel<<<dim3(8, 64),   256, SMEM_FA>>>();
    mm_out   <<<dim3(8, 64),   128, SMEM_2>>>(bo, out);
}